// round 9
// baseline (speedup 1.0000x reference)
#include <cuda_runtime.h>
#include <cuda_fp16.h>
#include <math.h>
#include <stdint.h>

#define B_    8
#define NTOK  2304
#define NROW  (B_*NTOK)      // 18432
#define HK    64
#define KD    16
#define VD    32
#define GM    (NTOK*KD)      // 36864
#define GN    (B_*VD)        // 256
#define GK    NTOK           // 2304
#define RTAB  (95*95*16)     // 144400

// ---------------- scratch (device globals; no allocations) ----------------
__device__ __align__(256) float g_q[(size_t)NROW*HK];
__device__ __align__(256) float g_kT[(size_t)B_*KD*NTOK];
__device__ __align__(256) float g_v[(size_t)NROW*VD];
__device__ __align__(256) float g_ksm[(size_t)B_*KD*NTOK];
__device__ __align__(256) float g_vt[(size_t)NTOK*GN];
__device__ __align__(256) unsigned short g_vthf[(size_t)GN*NTOK];      // [(b,v)][m] fp16
__device__ __align__(256) unsigned short g_Rh[RTAB];                   // rel-pos fp16
__device__ __align__(256) float g_part[288*224];
__device__ __align__(256) float g_lamc_part[(size_t)144*KD*VD];
__device__ __align__(256) float g_lamc[(size_t)B_*KD*VD];
__device__ __align__(256) float g_qaff[2*HK];
__device__ __align__(256) float g_vaff[2*VD];
__device__ __align__(256) float g_W3[128*128];                         // Wmp*Wcc [j][o2]
__device__ __align__(256) float g_lamp[(size_t)GM*GN];

// ---------------- portable PTX helpers ------------------------------------
__device__ __forceinline__ uint32_t smem_u32(const void* p) {
    uint32_t a;
    asm("{ .reg .u64 t; cvta.to.shared.u64 t, %1; cvt.u32.u64 %0, t; }" : "=r"(a) : "l"(p));
    return a;
}
__device__ __forceinline__ void ldmx4(uint32_t* r, uint32_t addr) {
    asm volatile("ldmatrix.sync.aligned.m8n8.x4.shared.b16 {%0,%1,%2,%3}, [%4];"
        : "=r"(r[0]), "=r"(r[1]), "=r"(r[2]), "=r"(r[3]) : "r"(addr));
}
__device__ __forceinline__ void mma16816(float* d, const uint32_t* a, uint32_t b0, uint32_t b1) {
    asm volatile("mma.sync.aligned.m16n8k16.row.col.f32.f16.f16.f32 "
        "{%0,%1,%2,%3}, {%4,%5,%6,%7}, {%8,%9}, {%0,%1,%2,%3};"
        : "+f"(d[0]), "+f"(d[1]), "+f"(d[2]), "+f"(d[3])
        : "r"(a[0]), "r"(a[1]), "r"(a[2]), "r"(a[3]), "r"(b0), "r"(b1));
}
__device__ __forceinline__ void cp16(uint32_t saddr, const void* g) {
    asm volatile("cp.async.cg.shared.global [%0], [%1], 16;" :: "r"(saddr), "l"(g));
}
#define CP_COMMIT() asm volatile("cp.async.commit_group;" ::: "memory")
#define CP_WAIT1()  asm volatile("cp.async.wait_group 1;" ::: "memory")
#define CP_WAIT0()  asm volatile("cp.async.wait_group 0;" ::: "memory")

// ---------------- K1: q/k/v 1x1 conv + BN partials + R convert ------------
// blocks 0..287: GEMM 64x112 tile, 224 thr, 8x4 per thread, vectorized LDS.
// blocks 288..932: fp16-convert R table.
#define XS_STR 68
#define WS_STR 116
__global__ void __launch_bounds__(224) k_proj(const float* __restrict__ x,
                       const float* __restrict__ Wq,
                       const float* __restrict__ Wk,
                       const float* __restrict__ Wv,
                       const float* __restrict__ R) {
    if (blockIdx.x >= 288) {
        int i = (blockIdx.x - 288)*224 + threadIdx.x;
        if (i < RTAB) g_Rh[i] = __half_as_ushort(__float2half_rn(R[i]));
        return;
    }
    __shared__ float Xs[32*XS_STR];
    __shared__ float Ws2[32*WS_STR];
    __shared__ float red[8*112];
    int t = threadIdx.x;
    int ty = t / 28, tx = t - ty*28;       // ty<8 (8 rows each), tx<28 (4 cols each)
    int row0 = blockIdx.x * 64;
    int bs = blockIdx.x / 36;
    float acc[8][4];
    #pragma unroll
    for (int i = 0; i < 8; i++)
        #pragma unroll
        for (int j = 0; j < 4; j++) acc[i][j] = 0.f;

    for (int k0 = 0; k0 < 128; k0 += 32) {
        for (int e = t; e < 2048; e += 224) {
            int r = e >> 5, k = e & 31;
            Xs[k*XS_STR + r] = x[(size_t)(row0+r)*128 + k0 + k];
        }
        for (int e = t; e < 3584; e += 224) {
            int o = e >> 5, k = e & 31;
            float w;
            if (o < 64)      w = Wq[o*128 + k0 + k];
            else if (o < 80) w = Wk[(o-64)*128 + k0 + k];
            else             w = Wv[(o-80)*128 + k0 + k];
            Ws2[k*WS_STR + o] = w;
        }
        __syncthreads();
        #pragma unroll 8
        for (int kk = 0; kk < 32; kk++) {
            float4 a0 = *(const float4*)&Xs[kk*XS_STR + ty*8];
            float4 a1 = *(const float4*)&Xs[kk*XS_STR + ty*8 + 4];
            float4 bv4 = *(const float4*)&Ws2[kk*WS_STR + tx*4];
            float a[8] = {a0.x,a0.y,a0.z,a0.w,a1.x,a1.y,a1.z,a1.w};
            float b[4] = {bv4.x,bv4.y,bv4.z,bv4.w};
            #pragma unroll
            for (int i = 0; i < 8; i++)
                #pragma unroll
                for (int j = 0; j < 4; j++) acc[i][j] += a[i]*b[j];
        }
        __syncthreads();
    }

    int db = (bs + 4) & 7;
    #pragma unroll
    for (int i = 0; i < 8; i++) {
        int row = row0 + ty*8 + i;
        int n = row - bs*NTOK;
        if (tx < 16) {
            *(float4*)&g_q[(size_t)row*64 + tx*4] =
                make_float4(acc[i][0], acc[i][1], acc[i][2], acc[i][3]);
        } else if (tx < 20) {
            int kd0 = (tx - 16)*4;
            #pragma unroll
            for (int j = 0; j < 4; j++)
                g_kT[(size_t)(db*16 + kd0 + j)*NTOK + n] = acc[i][j];
        } else {
            int vd0 = (tx - 20)*4;
            *(float4*)&g_v[((size_t)db*NTOK + n)*32 + vd0] =
                make_float4(acc[i][0], acc[i][1], acc[i][2], acc[i][3]);
        }
    }
    // BN partials
    float ps[4], pq[4];
    #pragma unroll
    for (int j = 0; j < 4; j++) {
        float s = 0.f, q2 = 0.f;
        #pragma unroll
        for (int i = 0; i < 8; i++) { s += acc[i][j]; q2 += acc[i][j]*acc[i][j]; }
        ps[j] = s; pq[j] = q2;
    }
    #pragma unroll
    for (int j = 0; j < 4; j++) red[ty*112 + tx*4 + j] = ps[j];
    __syncthreads();
    if (t < 112) {
        float s = 0.f;
        #pragma unroll
        for (int yy = 0; yy < 8; yy++) s += red[yy*112 + t];
        g_part[blockIdx.x*224 + t] = s;
    }
    __syncthreads();
    #pragma unroll
    for (int j = 0; j < 4; j++) red[ty*112 + tx*4 + j] = pq[j];
    __syncthreads();
    if (t < 112) {
        float s = 0.f;
        #pragma unroll
        for (int yy = 0; yy < 8; yy++) s += red[yy*112 + t];
        g_part[blockIdx.x*224 + 112 + t] = s;
    }
}

// ---------------- K2: reduce BN partials -> affine -------------------------
__global__ void k_affine(const float* __restrict__ gq, const float* __restrict__ bq,
                         const float* __restrict__ gv, const float* __restrict__ bv) {
    int t = threadIdx.x;
    if (t >= 112 || (t >= 64 && t < 80)) return;
    float s = 0.f, s2 = 0.f;
    for (int i = 0; i < 288; i++) {
        s  += g_part[i*224 + t];
        s2 += g_part[i*224 + 112 + t];
    }
    float mu  = s / (float)NROW;
    float var = s2 / (float)NROW - mu*mu;
    if (t < 64) {
        float sc = gq[t] * rsqrtf(var + 1e-5f);
        g_qaff[t] = sc; g_qaff[64+t] = bq[t] - mu*sc;
    } else {
        int c = t - 80;
        float sc = gv[c] * rsqrtf(var + 1e-5f);
        g_vaff[c] = sc; g_vaff[32+c] = bv[c] - mu*sc;
    }
}

// ---------------- K3b: BN(V) -> fp32 [m][col] + fp16 [col][m] -------------
__global__ void k_vt() {
    __shared__ unsigned short sh[64][33];
    int t = threadIdx.x;
    int cg = blockIdx.x & 3, mg = blockIdx.x >> 2;   // 4 x 72
    int col0 = cg*64, m0 = mg*32;
    for (int e = t; e < 2048; e += 256) {
        int lm = e >> 6, lc = e & 63;
        int col = col0 + lc;
        int b = col >> 5, v = col & 31;
        int m = m0 + lm;
        float xv = g_v[((size_t)b*NTOK + m)*32 + v] * g_vaff[v] + g_vaff[32+v];
        g_vt[(size_t)m*256 + col] = xv;
        sh[lc][lm] = __half_as_ushort(__float2half_rn(xv));
    }
    __syncthreads();
    int lc = t >> 2, sub = t & 3;
    uint32_t w[4];
    #pragma unroll
    for (int j = 0; j < 4; j++)
        w[j] = (uint32_t)sh[lc][sub*8 + 2*j] | ((uint32_t)sh[lc][sub*8 + 2*j+1] << 16);
    *(uint4*)(g_vthf + (size_t)(col0 + lc)*NTOK + m0 + sub*8) = make_uint4(w[0], w[1], w[2], w[3]);
}

// ---------------- K5: BIG GEMM via warp HMMA (fp16, 2 CTAs/SM) ------------
#define TK    64
#define NCH   (GK/TK)      // 36
#define AOFF  0
#define BOFF  16384
#define STG   32768
#define SMEM_MMA (2*STG)   // 65536

__global__ void __launch_bounds__(256, 2) k_lamp_hmma() {
    extern __shared__ char smem[];
    uint32_t sb = smem_u32(smem);
    int t = threadIdx.x;
    int nbase = blockIdx.y * 8;
    int col0  = blockIdx.x * 128;

    int n_loc = t >> 5, mi2 = t & 31;
    int n = nbase + n_loc;
    int n_row = n / 48, n_col = n - n_row*48;

    int wid = t >> 5, lane = t & 31;
    int wm = wid >> 1, wn = wid & 1;
    int lr = lane & 15, lc2 = (lane >> 4) * 16;

    float acc[2][8][4];
    #pragma unroll
    for (int i = 0; i < 2; i++)
        #pragma unroll
        for (int j = 0; j < 8; j++)
            #pragma unroll
            for (int q = 0; q < 4; q++) acc[i][j][q] = 0.f;

    uint4 ra0, ra1, rb0, rb1;

    auto ldgA = [&](int c) {
        int ma = c*TK + 2*mi2;
        int mr = ma / 48, mc2 = ma - mr*48;
        const uint4* pa = (const uint4*)(g_Rh + (size_t)((mr - n_row + 47)*95 + (mc2 - n_col + 47)) * 16);
        ra0 = pa[0]; ra1 = pa[1];
        int mb = ma + 1;
        mr = mb / 48; mc2 = mb - mr*48;
        const uint4* pb = (const uint4*)(g_Rh + (size_t)((mr - n_row + 47)*95 + (mc2 - n_col + 47)) * 16);
        rb0 = pb[0]; rb1 = pb[1];
    };
    auto stsA = [&](int p) {
        char* base = smem + p*STG + AOFF;
        uint32_t aw[8] = {ra0.x,ra0.y,ra0.z,ra0.w,ra1.x,ra1.y,ra1.z,ra1.w};
        uint32_t bw[8] = {rb0.x,rb0.y,rb0.z,rb0.w,rb1.x,rb1.y,rb1.z,rb1.w};
        uint32_t cb = (uint32_t)mi2 * 4;
        #pragma unroll
        for (int i = 0; i < 8; i++) {
            uint32_t w0 = __byte_perm(aw[i], bw[i], 0x5410);
            uint32_t w1 = __byte_perm(aw[i], bw[i], 0x7632);
            uint32_t r0 = (uint32_t)(n_loc*16 + 2*i);
            uint32_t r1 = r0 + 1;
            *(uint32_t*)(base + ((r0*128u + cb) ^ ((r0 & 7u) << 4))) = w0;
            *(uint32_t*)(base + ((r1*128u + cb) ^ ((r1 & 7u) << 4))) = w1;
        }
    };
    auto cpB = [&](int c, int p) {
        int m0 = c * TK;
        uint32_t sa = sb + p*STG + BOFF;
        #pragma unroll
        for (int i = 0; i < 4; i++) {
            int idx = t*4 + i;
            uint32_t col = (uint32_t)(idx >> 3), ch = (uint32_t)(idx & 7);
            uint32_t off = (col*128u + ch*16u) ^ ((col & 7u) << 4);
            cp16(sa + off, g_vthf + (size_t)(col0 + col)*NTOK + m0 + ch*8);
        }
    };

    // prologue
    ldgA(0); cpB(0, 0); CP_COMMIT(); stsA(0);
    ldgA(1); cpB(1, 1); CP_COMMIT();
    CP_WAIT1();
    __syncthreads();

    int p = 0;
    for (int c = 0; c < NCH; c++) {
        // A(c+1) into the other stage (its old A is dead past the last barrier)
        if (c + 1 < NCH) stsA(1 - p);
        if (c + 2 < NCH) ldgA(c + 2);

        uint32_t sa = sb + p*STG;
        #pragma unroll
        for (int kk = 0; kk < 4; kk++) {
            uint32_t kb = (uint32_t)(kk * 32);
            uint32_t aa[8], bb[16];
            #pragma unroll
            for (int mf = 0; mf < 2; mf++) {
                uint32_t row = (uint32_t)(wm*32 + mf*16 + lr);
                uint32_t off = (row*128u + kb + (uint32_t)lc2) ^ ((row & 7u) << 4);
                ldmx4(aa + mf*4, sa + AOFF + off);
            }
            #pragma unroll
            for (int ng = 0; ng < 4; ng++) {
                uint32_t row = (uint32_t)(wn*64 + ng*16 + lr);
                uint32_t off = (row*128u + kb + (uint32_t)lc2) ^ ((row & 7u) << 4);
                ldmx4(bb + ng*4, sa + BOFF + off);
            }
            #pragma unroll
            for (int mf = 0; mf < 2; mf++)
                #pragma unroll
                for (int nf = 0; nf < 8; nf++)
                    mma16816(acc[mf][nf], aa + mf*4, bb[(nf>>1)*4 + (nf&1)], bb[(nf>>1)*4 + (nf&1) + 2]);
        }
        CP_WAIT0();
        __syncthreads();
        if (c + 2 < NCH) { cpB(c + 2, p); CP_COMMIT(); }
        p ^= 1;
    }

    #pragma unroll
    for (int mf = 0; mf < 2; mf++) {
        #pragma unroll
        for (int nf = 0; nf < 8; nf++) {
            int r0 = blockIdx.y*128 + wm*32 + mf*16 + (lane >> 2);
            int c0 = col0 + wn*64 + nf*8 + (lane & 3)*2;
            *(float2*)&g_lamp[(size_t)r0*256 + c0]     = make_float2(acc[mf][nf][0], acc[mf][nf][1]);
            *(float2*)&g_lamp[(size_t)(r0+8)*256 + c0] = make_float2(acc[mf][nf][2], acc[mf][nf][3]);
        }
    }
}

// ---------------- K_W3: W3[j][o2] = sum_c Wmp[o2][c] * Wcc[c][j] ----------
__global__ void k_W3(const float* __restrict__ Wcc, const float* __restrict__ Wmp) {
    __shared__ float wj[64];
    int j = blockIdx.x, t = threadIdx.x;     // 128 blocks x 128 threads
    if (t < 64) wj[t] = Wcc[t*128 + j];
    __syncthreads();
    float s = 0.f;
    #pragma unroll 8
    for (int c = 0; c < 64; c++) s += Wmp[t*64 + c] * wj[c];
    g_W3[j*128 + t] = s;
}

// ---------------- K3: softmax over m ---------------------------------------
__global__ void k_softmax() {
    __shared__ float red[256];
    int bk = blockIdx.x, t = threadIdx.x;
    const float* src = g_kT + (size_t)bk*NTOK;
    float r[9];
    #pragma unroll
    for (int i = 0; i < 9; i++) r[i] = src[t + i*256];
    float mx = r[0];
    #pragma unroll
    for (int i = 1; i < 9; i++) mx = fmaxf(mx, r[i]);
    red[t] = mx; __syncthreads();
    for (int s = 128; s > 0; s >>= 1) { if (t < s) red[t] = fmaxf(red[t], red[t+s]); __syncthreads(); }
    mx = red[0]; __syncthreads();
    float sum = 0.f;
    #pragma unroll
    for (int i = 0; i < 9; i++) { r[i] = expf(r[i] - mx); sum += r[i]; }
    red[t] = sum; __syncthreads();
    for (int s = 128; s > 0; s >>= 1) { if (t < s) red[t] += red[t+s]; __syncthreads(); }
    float inv = 1.0f / red[0];
    float* dst = g_ksm + (size_t)bk*NTOK;
    #pragma unroll
    for (int i = 0; i < 9; i++) dst[t + i*256] = r[i] * inv;
}

// ---------------- K4: content lambda lamc ---------------------------------
__global__ void k_lamc_part() {
    __shared__ float Ks[16*128];
    __shared__ float Vs[128*32];
    int b = blockIdx.x / 18, mc = blockIdx.x - b*18;
    int m0 = mc * 128;
    int t = threadIdx.x;
    for (int i = t; i < 2048; i += 512) { int k = i>>7, mm = i&127; Ks[i] = g_ksm[(size_t)(b*16+k)*NTOK + m0+mm]; }
    for (int i = t; i < 4096; i += 512) { int mm = i>>5, v = i&31;  Vs[i] = g_vt[(size_t)(m0+mm)*256 + b*32 + v]; }
    __syncthreads();
    int k = t >> 5, v = t & 31;
    float acc = 0.f;
    #pragma unroll 8
    for (int mm = 0; mm < 128; mm++) acc += Ks[k*128+mm] * Vs[mm*32+v];
    g_lamc_part[(size_t)blockIdx.x*512 + t] = acc;
}
__global__ void k_lamc_red() {
    int b = blockIdx.x, t = threadIdx.x;
    float s = 0.f;
    for (int mc = 0; mc < 18; mc++) s += g_lamc_part[(size_t)(b*18+mc)*512 + t];
    g_lamc[b*512 + t] = s;
}

// ---------------- K6: consumers (W3-fused, 32 rows/block) -----------------
#define KO_W3T   0
#define KO_WMPT  16512
#define KO_WCE   24768
#define KO_BCE   24896
#define KO_BMP   24960
#define KO_LAMC  25088
#define KO_GRP   25600
#define KO_TOT   (25600 + 2*772)    // 27144 floats

__global__ void k_out(const float* __restrict__ cor,
                      const float* __restrict__ Wce, const float* __restrict__ bce,
                      const float* __restrict__ Wmp, const float* __restrict__ bmp,
                      float* __restrict__ app, float* __restrict__ mot) {
    extern __shared__ float sm[];
    float* W3T   = sm + KO_W3T;    // [128 j][129]
    float* WmpT  = sm + KO_WMPT;   // [64 c][129]
    float* WceS  = sm + KO_WCE;
    float* bceS  = sm + KO_BCE;
    float* bmpS  = sm + KO_BMP;
    float* lamcS = sm + KO_LAMC;
    float* grp   = sm + KO_GRP;
    int t = threadIdx.x;
    int g = t >> 7, t1 = t & 127;
    int b = (blockIdx.x * 32) / NTOK;

    for (int i = t; i < 16384; i += 256) W3T[(i>>7)*129 + (i&127)] = g_W3[i];
    for (int i = t; i < 8192; i += 256)  { int o = i>>6, c = i&63; WmpT[c*129 + o] = Wmp[i]; }
    if (t < 128) WceS[t] = Wce[t];
    if (t < 64)  bceS[t] = bce[t];
    if (t < 128) bmpS[t] = bmp[t];
    for (int i = t; i < 512; i += 256) lamcS[i] = g_lamc[b*512 + i];
    __syncthreads();

    float* Qn   = grp + g*772;
    float* ceS  = Qn + 64;
    float* Ltot = ceS + 64;        // 512
    float* crow = Ltot + 512;      // 128

    for (int it = 0; it < 16; it++) {
        int row = blockIdx.x*32 + it*2 + g;
        int n = row - b*NTOK;
        for (int i = t1; i < 512; i += 128) {
            int k = i >> 5, v = i & 31;
            Ltot[i] = lamcS[i] + g_lamp[(size_t)(n*16 + k)*256 + b*32 + v];
        }
        if (t1 < 64) {
            Qn[t1] = g_q[(size_t)row*64 + t1] * g_qaff[t1] + g_qaff[64+t1];
        } else {
            int o = t1 - 64;
            float c0 = cor[(size_t)row*2], c1 = cor[(size_t)row*2 + 1];
            ceS[o] = c0*WceS[o*2] + c1*WceS[o*2+1] + bceS[o];
        }
        __syncthreads();
        {
            int h = t1 >> 5, v = t1 & 31;
            float y = 0.f, cr = 0.f;
            #pragma unroll
            for (int k = 0; k < 16; k++) {
                float a = Ltot[k*32 + v];
                y  += Qn[h*16 + k]  * a;
                cr += ceS[h*16 + k] * a;
            }
            app[(size_t)row*128 + t1] = y;
            crow[t1] = cr;
        }
        __syncthreads();
        {
            float s = bmpS[t1];
            #pragma unroll 4
            for (int j = 0; j < 128; j++) s += crow[j] * W3T[j*129 + t1];
            #pragma unroll 4
            for (int c = 0; c < 64; c++)  s -= ceS[c] * WmpT[c*129 + t1];
            mot[(size_t)row*128 + t1] = s;
        }
        __syncthreads();
    }
}

// ---------------- launch ---------------------------------------------------
extern "C" void kernel_launch(void* const* d_in, const int* in_sizes, int n_in,
                              void* d_out, int out_size) {
    const float* x   = (const float*)d_in[0];
    const float* cor = (const float*)d_in[1];
    const float* Wq  = (const float*)d_in[2];
    const float* Wk  = (const float*)d_in[3];
    const float* Wv  = (const float*)d_in[4];
    const float* Wce = (const float*)d_in[5];
    const float* bce = (const float*)d_in[6];
    const float* Wcc = (const float*)d_in[7];
    const float* Wmp = (const float*)d_in[8];
    const float* bmp = (const float*)d_in[9];
    const float* gq  = (const float*)d_in[10];
    const float* bq  = (const float*)d_in[11];
    const float* gv  = (const float*)d_in[12];
    const float* bv  = (const float*)d_in[13];
    const float* rpe = (const float*)d_in[14];
    float* app = (float*)d_out;
    float* mot = app + (size_t)NROW*128;

    cudaFuncSetAttribute(k_out, cudaFuncAttributeMaxDynamicSharedMemorySize, KO_TOT*4);
    cudaFuncSetAttribute(k_lamp_hmma, cudaFuncAttributeMaxDynamicSharedMemorySize, SMEM_MMA);

    k_proj<<<288 + (RTAB + 223)/224, 224>>>(x, Wq, Wk, Wv, rpe);  // #1
    k_affine<<<1, 128>>>(gq, bq, gv, bv);                          // #2
    k_vt<<<288, 256>>>();                                          // #3
    k_lamp_hmma<<<dim3(2, 288), 256, SMEM_MMA>>>();                // #4 <- profiled
    k_W3<<<128, 128>>>(Wcc, Wmp);                                  // #5
    k_softmax<<<128, 256>>>();                                     // #6
    k_lamc_part<<<144, 512>>>();                                   // #7
    k_lamc_red<<<8, 512>>>();                                      // #8
    k_out<<<576, 256, KO_TOT*4>>>(cor, Wce, bce, Wmp, bmp, app, mot);  // #9
}

// round 10
// speedup vs baseline: 1.2882x; 1.2882x over previous
#include <cuda_runtime.h>
#include <cuda_fp16.h>
#include <math.h>
#include <stdint.h>

#define B_    8
#define NTOK  2304
#define NROW  (B_*NTOK)      // 18432
#define HK    64
#define KD    16
#define VD    32
#define GM    (NTOK*KD)      // 36864
#define GN    (B_*VD)        // 256
#define GK    NTOK           // 2304
#define RTAB  (95*95*16)     // 144400

// ---------------- scratch (device globals; no allocations) ----------------
__device__ __align__(256) float g_q[(size_t)NROW*HK];
__device__ __align__(256) float g_kT[(size_t)B_*KD*NTOK];
__device__ __align__(256) float g_v[(size_t)NROW*VD];
__device__ __align__(256) float g_ksm[(size_t)B_*KD*NTOK];
__device__ __align__(256) float g_vt[(size_t)NTOK*GN];
__device__ __align__(256) unsigned short g_vthf[(size_t)GN*NTOK];      // [(b,v)][m] fp16
__device__ __align__(256) unsigned short g_Rh[RTAB];                   // rel-pos fp16
__device__ __align__(256) float g_part[288*224];
__device__ __align__(256) float g_lamc_part[(size_t)144*KD*VD];
__device__ __align__(256) float g_lamc[(size_t)B_*KD*VD];
__device__ __align__(256) float g_qaff[2*HK];
__device__ __align__(256) float g_vaff[2*VD];
__device__ __align__(256) float g_dif[(size_t)NROW*64];
__device__ __align__(256) float g_lamp[(size_t)GM*GN];

// ---------------- portable PTX helpers ------------------------------------
__device__ __forceinline__ uint32_t smem_u32(const void* p) {
    uint32_t a;
    asm("{ .reg .u64 t; cvta.to.shared.u64 t, %1; cvt.u32.u64 %0, t; }" : "=r"(a) : "l"(p));
    return a;
}
__device__ __forceinline__ void ldmx4(uint32_t* r, uint32_t addr) {
    asm volatile("ldmatrix.sync.aligned.m8n8.x4.shared.b16 {%0,%1,%2,%3}, [%4];"
        : "=r"(r[0]), "=r"(r[1]), "=r"(r[2]), "=r"(r[3]) : "r"(addr));
}
__device__ __forceinline__ void mma16816(float* d, const uint32_t* a, uint32_t b0, uint32_t b1) {
    asm volatile("mma.sync.aligned.m16n8k16.row.col.f32.f16.f16.f32 "
        "{%0,%1,%2,%3}, {%4,%5,%6,%7}, {%8,%9}, {%0,%1,%2,%3};"
        : "+f"(d[0]), "+f"(d[1]), "+f"(d[2]), "+f"(d[3])
        : "r"(a[0]), "r"(a[1]), "r"(a[2]), "r"(a[3]), "r"(b0), "r"(b1));
}
__device__ __forceinline__ void cp16(uint32_t saddr, const void* g) {
    asm volatile("cp.async.cg.shared.global [%0], [%1], 16;" :: "r"(saddr), "l"(g));
}
#define CP_COMMIT() asm volatile("cp.async.commit_group;" ::: "memory")
#define CP_WAIT1()  asm volatile("cp.async.wait_group 1;" ::: "memory")
#define CP_WAIT0()  asm volatile("cp.async.wait_group 0;" ::: "memory")

// ---------------- K1: q/k/v 1x1 conv + BN partials + R convert (R8) -------
__global__ void __launch_bounds__(256) k_proj(const float* __restrict__ x,
                       const float* __restrict__ Wq,
                       const float* __restrict__ Wk,
                       const float* __restrict__ Wv,
                       const float* __restrict__ R) {
    if (blockIdx.x >= 288) {
        int i = (blockIdx.x - 288)*256 + threadIdx.x;
        if (i < RTAB) g_Rh[i] = __half_as_ushort(__float2half_rn(R[i]));
        return;
    }
    __shared__ float Xs[64*33];
    __shared__ float Ws2[112*33];
    __shared__ float red[16*112];
    int t = threadIdx.x;
    int ty = t >> 4, tx = t & 15;
    int row0 = blockIdx.x * 64;
    int bs = blockIdx.x / 36;
    float acc[4][7];
    #pragma unroll
    for (int i = 0; i < 4; i++)
        #pragma unroll
        for (int j = 0; j < 7; j++) acc[i][j] = 0.f;

    for (int k0 = 0; k0 < 128; k0 += 32) {
        for (int e = t; e < 2048; e += 256) {
            int r = e >> 5, k = e & 31;
            Xs[r*33 + k] = x[(size_t)(row0+r)*128 + k0 + k];
        }
        for (int e = t; e < 3584; e += 256) {
            int o = e >> 5, k = e & 31;
            float w;
            if (o < 64)      w = Wq[o*128 + k0 + k];
            else if (o < 80) w = Wk[(o-64)*128 + k0 + k];
            else             w = Wv[(o-80)*128 + k0 + k];
            Ws2[o*33 + k] = w;
        }
        __syncthreads();
        #pragma unroll 8
        for (int kk = 0; kk < 32; kk++) {
            float a[4], b[7];
            #pragma unroll
            for (int i = 0; i < 4; i++) a[i] = Xs[(ty*4+i)*33 + kk];
            #pragma unroll
            for (int j = 0; j < 7; j++) b[j] = Ws2[(tx*7+j)*33 + kk];
            #pragma unroll
            for (int i = 0; i < 4; i++)
                #pragma unroll
                for (int j = 0; j < 7; j++) acc[i][j] += a[i]*b[j];
        }
        __syncthreads();
    }

    int db = (bs + 4) & 7;
    #pragma unroll
    for (int i = 0; i < 4; i++) {
        int row = row0 + ty*4 + i;
        int n = row - bs*NTOK;
        #pragma unroll
        for (int j = 0; j < 7; j++) {
            int o = tx*7 + j;
            float val = acc[i][j];
            if (o < 64)       g_q[(size_t)row*64 + o] = val;
            else if (o < 80)  g_kT[(size_t)(db*16 + o-64)*NTOK + n] = val;
            else              g_v[((size_t)db*NTOK + n)*32 + (o-80)] = val;
        }
    }
    float ps[7], pq[7];
    #pragma unroll
    for (int j = 0; j < 7; j++) {
        ps[j] = acc[0][j]+acc[1][j]+acc[2][j]+acc[3][j];
        pq[j] = acc[0][j]*acc[0][j]+acc[1][j]*acc[1][j]+acc[2][j]*acc[2][j]+acc[3][j]*acc[3][j];
    }
    #pragma unroll
    for (int j = 0; j < 7; j++) red[ty*112 + tx*7 + j] = ps[j];
    __syncthreads();
    if (t < 112) {
        float s = 0.f;
        #pragma unroll
        for (int yy = 0; yy < 16; yy++) s += red[yy*112 + t];
        g_part[blockIdx.x*224 + t] = s;
    }
    __syncthreads();
    #pragma unroll
    for (int j = 0; j < 7; j++) red[ty*112 + tx*7 + j] = pq[j];
    __syncthreads();
    if (t < 112) {
        float s = 0.f;
        #pragma unroll
        for (int yy = 0; yy < 16; yy++) s += red[yy*112 + t];
        g_part[blockIdx.x*224 + 112 + t] = s;
    }
}

// ---------------- K2: reduce BN partials -> affine -------------------------
__global__ void k_affine(const float* __restrict__ gq, const float* __restrict__ bq,
                         const float* __restrict__ gv, const float* __restrict__ bv) {
    int t = threadIdx.x;
    if (t >= 112 || (t >= 64 && t < 80)) return;
    float s = 0.f, s2 = 0.f;
    for (int i = 0; i < 288; i++) {
        s  += g_part[i*224 + t];
        s2 += g_part[i*224 + 112 + t];
    }
    float mu  = s / (float)NROW;
    float var = s2 / (float)NROW - mu*mu;
    if (t < 64) {
        float sc = gq[t] * rsqrtf(var + 1e-5f);
        g_qaff[t] = sc; g_qaff[64+t] = bq[t] - mu*sc;
    } else {
        int c = t - 80;
        float sc = gv[c] * rsqrtf(var + 1e-5f);
        g_vaff[c] = sc; g_vaff[32+c] = bv[c] - mu*sc;
    }
}

// ---------------- K3b: BN(V) -> fp32 [m][col] + fp16 [col][m] -------------
__global__ void k_vt() {
    __shared__ unsigned short sh[64][33];
    int t = threadIdx.x;
    int cg = blockIdx.x & 3, mg = blockIdx.x >> 2;   // 4 x 72
    int col0 = cg*64, m0 = mg*32;
    for (int e = t; e < 2048; e += 256) {
        int lm = e >> 6, lc = e & 63;
        int col = col0 + lc;
        int b = col >> 5, v = col & 31;
        int m = m0 + lm;
        float xv = g_v[((size_t)b*NTOK + m)*32 + v] * g_vaff[v] + g_vaff[32+v];
        g_vt[(size_t)m*256 + col] = xv;
        sh[lc][lm] = __half_as_ushort(__float2half_rn(xv));
    }
    __syncthreads();
    int lc = t >> 2, sub = t & 3;
    uint32_t w[4];
    #pragma unroll
    for (int j = 0; j < 4; j++)
        w[j] = (uint32_t)sh[lc][sub*8 + 2*j] | ((uint32_t)sh[lc][sub*8 + 2*j+1] << 16);
    *(uint4*)(g_vthf + (size_t)(col0 + lc)*NTOK + m0 + sub*8) = make_uint4(w[0], w[1], w[2], w[3]);
}

// ---------------- K5: BIG GEMM via warp HMMA (fp16, 2 CTAs/SM, R8) --------
#define TK    64
#define NCH   (GK/TK)      // 36
#define AOFF  0
#define BOFF  16384
#define STG   32768
#define SMEM_MMA (2*STG)   // 65536

__global__ void __launch_bounds__(256, 2) k_lamp_hmma() {
    extern __shared__ char smem[];
    uint32_t sb = smem_u32(smem);
    int t = threadIdx.x;
    int nbase = blockIdx.y * 8;
    int col0  = blockIdx.x * 128;

    int n_loc = t >> 5, mi2 = t & 31;
    int n = nbase + n_loc;
    int n_row = n / 48, n_col = n - n_row*48;

    int wid = t >> 5, lane = t & 31;
    int wm = wid >> 1, wn = wid & 1;
    int lr = lane & 15, lc2 = (lane >> 4) * 16;

    float acc[2][8][4];
    #pragma unroll
    for (int i = 0; i < 2; i++)
        #pragma unroll
        for (int j = 0; j < 8; j++)
            #pragma unroll
            for (int q = 0; q < 4; q++) acc[i][j][q] = 0.f;

    uint4 ra0, ra1, rb0, rb1;

    auto ldgA = [&](int c) {
        int ma = c*TK + 2*mi2;
        int mr = ma / 48, mc2 = ma - mr*48;
        const uint4* pa = (const uint4*)(g_Rh + (size_t)((mr - n_row + 47)*95 + (mc2 - n_col + 47)) * 16);
        ra0 = pa[0]; ra1 = pa[1];
        int mb = ma + 1;
        mr = mb / 48; mc2 = mb - mr*48;
        const uint4* pb = (const uint4*)(g_Rh + (size_t)((mr - n_row + 47)*95 + (mc2 - n_col + 47)) * 16);
        rb0 = pb[0]; rb1 = pb[1];
    };
    auto stsA = [&](int p) {
        char* base = smem + p*STG + AOFF;
        uint32_t aw[8] = {ra0.x,ra0.y,ra0.z,ra0.w,ra1.x,ra1.y,ra1.z,ra1.w};
        uint32_t bw[8] = {rb0.x,rb0.y,rb0.z,rb0.w,rb1.x,rb1.y,rb1.z,rb1.w};
        uint32_t cb = (uint32_t)mi2 * 4;
        #pragma unroll
        for (int i = 0; i < 8; i++) {
            uint32_t w0 = __byte_perm(aw[i], bw[i], 0x5410);
            uint32_t w1 = __byte_perm(aw[i], bw[i], 0x7632);
            uint32_t r0 = (uint32_t)(n_loc*16 + 2*i);
            uint32_t r1 = r0 + 1;
            *(uint32_t*)(base + ((r0*128u + cb) ^ ((r0 & 7u) << 4))) = w0;
            *(uint32_t*)(base + ((r1*128u + cb) ^ ((r1 & 7u) << 4))) = w1;
        }
    };
    auto cpB = [&](int c, int p) {
        int m0 = c * TK;
        uint32_t sa = sb + p*STG + BOFF;
        #pragma unroll
        for (int i = 0; i < 4; i++) {
            int idx = t*4 + i;
            uint32_t col = (uint32_t)(idx >> 3), ch = (uint32_t)(idx & 7);
            uint32_t off = (col*128u + ch*16u) ^ ((col & 7u) << 4);
            cp16(sa + off, g_vthf + (size_t)(col0 + col)*NTOK + m0 + ch*8);
        }
    };

    // prologue
    ldgA(0); cpB(0, 0); CP_COMMIT(); stsA(0);
    ldgA(1); cpB(1, 1); CP_COMMIT();
    CP_WAIT1();
    __syncthreads();

    int p = 0;
    for (int c = 0; c < NCH; c++) {
        uint32_t sa = sb + p*STG;
        #pragma unroll
        for (int kk = 0; kk < 4; kk++) {
            uint32_t kb = (uint32_t)(kk * 32);
            uint32_t aa[8], bb[16];
            #pragma unroll
            for (int mf = 0; mf < 2; mf++) {
                uint32_t row = (uint32_t)(wm*32 + mf*16 + lr);
                uint32_t off = (row*128u + kb + (uint32_t)lc2) ^ ((row & 7u) << 4);
                ldmx4(aa + mf*4, sa + AOFF + off);
            }
            #pragma unroll
            for (int ng = 0; ng < 4; ng++) {
                uint32_t row = (uint32_t)(wn*64 + ng*16 + lr);
                uint32_t off = (row*128u + kb + (uint32_t)lc2) ^ ((row & 7u) << 4);
                ldmx4(bb + ng*4, sa + BOFF + off);
            }
            #pragma unroll
            for (int mf = 0; mf < 2; mf++)
                #pragma unroll
                for (int nf = 0; nf < 8; nf++)
                    mma16816(acc[mf][nf], aa + mf*4, bb[(nf>>1)*4 + (nf&1)], bb[(nf>>1)*4 + (nf&1) + 2]);
        }
        if (c + 1 < NCH) stsA(1 - p);
        if (c + 2 < NCH) ldgA(c + 2);
        CP_WAIT0();
        __syncthreads();
        if (c + 2 < NCH) { cpB(c + 2, p); CP_COMMIT(); }
        p ^= 1;
    }

    #pragma unroll
    for (int mf = 0; mf < 2; mf++) {
        #pragma unroll
        for (int nf = 0; nf < 8; nf++) {
            int r0 = blockIdx.y*128 + wm*32 + mf*16 + (lane >> 2);
            int c0 = col0 + wn*64 + nf*8 + (lane & 3)*2;
            *(float2*)&g_lamp[(size_t)r0*256 + c0]     = make_float2(acc[mf][nf][0], acc[mf][nf][1]);
            *(float2*)&g_lamp[(size_t)(r0+8)*256 + c0] = make_float2(acc[mf][nf][2], acc[mf][nf][3]);
        }
    }
}

// ---------------- K3: softmax over m ---------------------------------------
__global__ void k_softmax() {
    __shared__ float red[256];
    int bk = blockIdx.x, t = threadIdx.x;
    const float* src = g_kT + (size_t)bk*NTOK;
    float r[9];
    #pragma unroll
    for (int i = 0; i < 9; i++) r[i] = src[t + i*256];
    float mx = r[0];
    #pragma unroll
    for (int i = 1; i < 9; i++) mx = fmaxf(mx, r[i]);
    red[t] = mx; __syncthreads();
    for (int s = 128; s > 0; s >>= 1) { if (t < s) red[t] = fmaxf(red[t], red[t+s]); __syncthreads(); }
    mx = red[0]; __syncthreads();
    float sum = 0.f;
    #pragma unroll
    for (int i = 0; i < 9; i++) { r[i] = expf(r[i] - mx); sum += r[i]; }
    red[t] = sum; __syncthreads();
    for (int s = 128; s > 0; s >>= 1) { if (t < s) red[t] += red[t+s]; __syncthreads(); }
    float inv = 1.0f / red[0];
    float* dst = g_ksm + (size_t)bk*NTOK;
    #pragma unroll
    for (int i = 0; i < 9; i++) dst[t + i*256] = r[i] * inv;
}

// ---------------- K4: content lambda lamc ---------------------------------
__global__ void k_lamc_part() {
    __shared__ float Ks[16*128];
    __shared__ float Vs[128*32];
    int b = blockIdx.x / 18, mc = blockIdx.x - b*18;
    int m0 = mc * 128;
    int t = threadIdx.x;
    for (int i = t; i < 2048; i += 512) { int k = i>>7, mm = i&127; Ks[i] = g_ksm[(size_t)(b*16+k)*NTOK + m0+mm]; }
    for (int i = t; i < 4096; i += 512) { int mm = i>>5, v = i&31;  Vs[i] = g_vt[(size_t)(m0+mm)*256 + b*32 + v]; }
    __syncthreads();
    int k = t >> 5, v = t & 31;
    float acc = 0.f;
    #pragma unroll 8
    for (int mm = 0; mm < 128; mm++) acc += Ks[k*128+mm] * Vs[mm*32+v];
    g_lamc_part[(size_t)blockIdx.x*512 + t] = acc;
}
__global__ void k_lamc_red() {
    int b = blockIdx.x, t = threadIdx.x;
    float s = 0.f;
    for (int mc = 0; mc < 18; mc++) s += g_lamc_part[(size_t)(b*18+mc)*512 + t];
    g_lamc[b*512 + t] = s;
}

// ---------------- K6a: app + dif (warp-per-row, sync-free) ----------------
__global__ void __launch_bounds__(256) k_outA(const float* __restrict__ cor,
                       const float* __restrict__ Wce, const float* __restrict__ bce,
                       const float* __restrict__ Wcc,
                       float* __restrict__ app) {
    __shared__ float WccS[64*129];   // [o][c] padded
    __shared__ float WceS[128];
    __shared__ float bceS[64];
    __shared__ float lamcS[512];
    int t = threadIdx.x;
    int b = blockIdx.x / 288;        // 288 blocks per batch (8 rows each)

    for (int i = t; i < 8192; i += 256) WccS[(i>>7)*129 + (i&127)] = Wcc[i];
    if (t < 128) WceS[t] = Wce[t];
    if (t < 64)  bceS[t] = bce[t];
    for (int i = t; i < 512; i += 256) lamcS[i] = g_lamc[b*512 + i];
    __syncthreads();

    int w = t >> 5, lane = t & 31;
    int row = blockIdx.x*8 + w;
    int n = row - b*NTOK;

    float q0 = g_q[(size_t)row*64 + lane]      * g_qaff[lane]    + g_qaff[64+lane];
    float q1 = g_q[(size_t)row*64 + 32 + lane] * g_qaff[32+lane] + g_qaff[96+lane];
    float c0 = cor[(size_t)row*2], c1 = cor[(size_t)row*2 + 1];
    float ce0 = c0*WceS[lane*2]      + c1*WceS[lane*2+1]      + bceS[lane];
    float ce1 = c0*WceS[(32+lane)*2] + c1*WceS[(32+lane)*2+1] + bceS[32+lane];

    float y[4] = {0.f,0.f,0.f,0.f}, cr[4] = {0.f,0.f,0.f,0.f};
    const float* lp = g_lamp + (size_t)(n*16)*256 + b*32 + lane;
    #pragma unroll
    for (int k = 0; k < 16; k++) {
        float l = lp[(size_t)k*256] + lamcS[k*32 + lane];
        y[0]  += __shfl_sync(0xffffffffu, q0, k)      * l;
        y[1]  += __shfl_sync(0xffffffffu, q0, 16 + k) * l;
        y[2]  += __shfl_sync(0xffffffffu, q1, k)      * l;
        y[3]  += __shfl_sync(0xffffffffu, q1, 16 + k) * l;
        cr[0] += __shfl_sync(0xffffffffu, ce0, k)      * l;
        cr[1] += __shfl_sync(0xffffffffu, ce0, 16 + k) * l;
        cr[2] += __shfl_sync(0xffffffffu, ce1, k)      * l;
        cr[3] += __shfl_sync(0xffffffffu, ce1, 16 + k) * l;
    }
    #pragma unroll
    for (int h = 0; h < 4; h++)
        app[(size_t)row*128 + h*32 + lane] = y[h];

    // dif[o] = sum_c crow[c]*Wcc[o][c] - ce[o], for o = lane and 32+lane
    float d0 = -ce0, d1 = -ce1;
    #pragma unroll 4
    for (int c = 0; c < 128; c++) {
        float crc = __shfl_sync(0xffffffffu, cr[c >> 5], c & 31);
        d0 += crc * WccS[lane*129 + c];
        d1 += crc * WccS[(32+lane)*129 + c];
    }
    g_dif[(size_t)row*64 + lane]      = d0;
    g_dif[(size_t)row*64 + 32 + lane] = d1;
}

// ---------------- K6b: mot = dif * Wmp^T + bmp ----------------------------
__global__ void __launch_bounds__(256) k_outB(const float* __restrict__ Wmp,
                       const float* __restrict__ bmp,
                       float* __restrict__ mot) {
    __shared__ float WmpS[128*65];   // [o][c] padded
    __shared__ float bmpS[128];
    int t = threadIdx.x;
    for (int i = t; i < 8192; i += 256) WmpS[(i>>6)*65 + (i&63)] = Wmp[i];
    if (t < 128) bmpS[t] = bmp[t];
    __syncthreads();

    int w = t >> 5, lane = t & 31;
    int row = blockIdx.x*8 + w;
    float d0 = g_dif[(size_t)row*64 + lane];
    float d1 = g_dif[(size_t)row*64 + 32 + lane];
    float m[4] = {bmpS[lane], bmpS[32+lane], bmpS[64+lane], bmpS[96+lane]};
    #pragma unroll 8
    for (int c = 0; c < 32; c++) {
        float dc = __shfl_sync(0xffffffffu, d0, c);
        #pragma unroll
        for (int h = 0; h < 4; h++) m[h] += dc * WmpS[(h*32+lane)*65 + c];
    }
    #pragma unroll 8
    for (int c = 0; c < 32; c++) {
        float dc = __shfl_sync(0xffffffffu, d1, c);
        #pragma unroll
        for (int h = 0; h < 4; h++) m[h] += dc * WmpS[(h*32+lane)*65 + 32 + c];
    }
    #pragma unroll
    for (int h = 0; h < 4; h++)
        mot[(size_t)row*128 + h*32 + lane] = m[h];
}

// ---------------- launch ---------------------------------------------------
extern "C" void kernel_launch(void* const* d_in, const int* in_sizes, int n_in,
                              void* d_out, int out_size) {
    const float* x   = (const float*)d_in[0];
    const float* cor = (const float*)d_in[1];
    const float* Wq  = (const float*)d_in[2];
    const float* Wk  = (const float*)d_in[3];
    const float* Wv  = (const float*)d_in[4];
    const float* Wce = (const float*)d_in[5];
    const float* bce = (const float*)d_in[6];
    const float* Wcc = (const float*)d_in[7];
    const float* Wmp = (const float*)d_in[8];
    const float* bmp = (const float*)d_in[9];
    const float* gq  = (const float*)d_in[10];
    const float* bq  = (const float*)d_in[11];
    const float* gv  = (const float*)d_in[12];
    const float* bv  = (const float*)d_in[13];
    const float* rpe = (const float*)d_in[14];
    float* app = (float*)d_out;
    float* mot = app + (size_t)NROW*128;

    cudaFuncSetAttribute(k_lamp_hmma, cudaFuncAttributeMaxDynamicSharedMemorySize, SMEM_MMA);

    k_proj<<<288 + (RTAB + 255)/256, 256>>>(x, Wq, Wk, Wv, rpe);  // #1
    k_affine<<<1, 128>>>(gq, bq, gv, bv);                          // #2
    k_vt<<<288, 256>>>();                                          // #3
    k_lamp_hmma<<<dim3(2, 288), 256, SMEM_MMA>>>();                // #4 <- profiled
    k_softmax<<<128, 256>>>();                                     // #5
    k_lamc_part<<<144, 512>>>();                                   // #6
    k_lamc_red<<<8, 512>>>();                                      // #7
    k_outA<<<NROW/8, 256>>>(cor, Wce, bce, Wcc, app);              // #8
    k_outB<<<NROW/8, 256>>>(Wmp, bmp, mot);                        // #9
}

// round 11
// speedup vs baseline: 1.3236x; 1.0274x over previous
#include <cuda_runtime.h>
#include <cuda_fp16.h>
#include <math.h>
#include <stdint.h>

#define B_    8
#define NTOK  2304
#define NROW  (B_*NTOK)      // 18432
#define HK    64
#define KD    16
#define VD    32
#define GM    (NTOK*KD)      // 36864
#define GN    (B_*VD)        // 256
#define GK    NTOK           // 2304
#define RTAB  (95*95*16)     // 144400

// ---------------- scratch (device globals; no allocations) ----------------
__device__ __align__(256) float g_q[(size_t)NROW*HK];
__device__ __align__(256) float g_kT[(size_t)B_*KD*NTOK];
__device__ __align__(256) float g_v[(size_t)NROW*VD];
__device__ __align__(256) float g_ksm[(size_t)B_*KD*NTOK];
__device__ __align__(256) float g_vt[(size_t)NTOK*GN];
__device__ __align__(256) unsigned short g_vthf[(size_t)GN*NTOK];      // [(b,v)][m] fp16
__device__ __align__(256) unsigned short g_Rh[RTAB];                   // rel-pos fp16
__device__ __align__(256) float g_part[288*224];
__device__ __align__(256) float g_lamc_part[(size_t)144*KD*VD];
__device__ __align__(256) float g_lamc[(size_t)B_*KD*VD];
__device__ __align__(256) float g_qaff[2*HK];
__device__ __align__(256) float g_vaff[2*VD];
__device__ __align__(256) float g_lamp[(size_t)GM*GN];

// ---------------- portable PTX helpers ------------------------------------
__device__ __forceinline__ uint32_t smem_u32(const void* p) {
    uint32_t a;
    asm("{ .reg .u64 t; cvta.to.shared.u64 t, %1; cvt.u32.u64 %0, t; }" : "=r"(a) : "l"(p));
    return a;
}
__device__ __forceinline__ void ldmx4(uint32_t* r, uint32_t addr) {
    asm volatile("ldmatrix.sync.aligned.m8n8.x4.shared.b16 {%0,%1,%2,%3}, [%4];"
        : "=r"(r[0]), "=r"(r[1]), "=r"(r[2]), "=r"(r[3]) : "r"(addr));
}
__device__ __forceinline__ void mma16816(float* d, const uint32_t* a, uint32_t b0, uint32_t b1) {
    asm volatile("mma.sync.aligned.m16n8k16.row.col.f32.f16.f16.f32 "
        "{%0,%1,%2,%3}, {%4,%5,%6,%7}, {%8,%9}, {%0,%1,%2,%3};"
        : "+f"(d[0]), "+f"(d[1]), "+f"(d[2]), "+f"(d[3])
        : "r"(a[0]), "r"(a[1]), "r"(a[2]), "r"(a[3]), "r"(b0), "r"(b1));
}
__device__ __forceinline__ void cp16(uint32_t saddr, const void* g) {
    asm volatile("cp.async.cg.shared.global [%0], [%1], 16;" :: "r"(saddr), "l"(g));
}
#define CP_COMMIT() asm volatile("cp.async.commit_group;" ::: "memory")
#define CP_WAIT1()  asm volatile("cp.async.wait_group 1;" ::: "memory")
#define CP_WAIT0()  asm volatile("cp.async.wait_group 0;" ::: "memory")

// ---------------- K1: q/k/v 1x1 conv + BN partials + R convert ------------
__global__ void __launch_bounds__(256) k_proj(const float* __restrict__ x,
                       const float* __restrict__ Wq,
                       const float* __restrict__ Wk,
                       const float* __restrict__ Wv,
                       const float* __restrict__ R) {
    if (blockIdx.x >= 288) {
        int i = (blockIdx.x - 288)*256 + threadIdx.x;
        if (i < RTAB) g_Rh[i] = __half_as_ushort(__float2half_rn(R[i]));
        return;
    }
    __shared__ float Xs[64*33];
    __shared__ float Ws2[112*33];
    __shared__ float red[16*112];
    int t = threadIdx.x;
    int ty = t >> 4, tx = t & 15;
    int row0 = blockIdx.x * 64;
    int bs = blockIdx.x / 36;
    float acc[4][7];
    #pragma unroll
    for (int i = 0; i < 4; i++)
        #pragma unroll
        for (int j = 0; j < 7; j++) acc[i][j] = 0.f;

    for (int k0 = 0; k0 < 128; k0 += 32) {
        for (int e = t; e < 2048; e += 256) {
            int r = e >> 5, k = e & 31;
            Xs[r*33 + k] = x[(size_t)(row0+r)*128 + k0 + k];
        }
        for (int e = t; e < 3584; e += 256) {
            int o = e >> 5, k = e & 31;
            float w;
            if (o < 64)      w = Wq[o*128 + k0 + k];
            else if (o < 80) w = Wk[(o-64)*128 + k0 + k];
            else             w = Wv[(o-80)*128 + k0 + k];
            Ws2[o*33 + k] = w;
        }
        __syncthreads();
        #pragma unroll 8
        for (int kk = 0; kk < 32; kk++) {
            float a[4], b[7];
            #pragma unroll
            for (int i = 0; i < 4; i++) a[i] = Xs[(ty*4+i)*33 + kk];
            #pragma unroll
            for (int j = 0; j < 7; j++) b[j] = Ws2[(tx*7+j)*33 + kk];
            #pragma unroll
            for (int i = 0; i < 4; i++)
                #pragma unroll
                for (int j = 0; j < 7; j++) acc[i][j] += a[i]*b[j];
        }
        __syncthreads();
    }

    int db = (bs + 4) & 7;
    #pragma unroll
    for (int i = 0; i < 4; i++) {
        int row = row0 + ty*4 + i;
        int n = row - bs*NTOK;
        #pragma unroll
        for (int j = 0; j < 7; j++) {
            int o = tx*7 + j;
            float val = acc[i][j];
            if (o < 64)       g_q[(size_t)row*64 + o] = val;
            else if (o < 80)  g_kT[(size_t)(db*16 + o-64)*NTOK + n] = val;
            else              g_v[((size_t)db*NTOK + n)*32 + (o-80)] = val;
        }
    }
    float ps[7], pq[7];
    #pragma unroll
    for (int j = 0; j < 7; j++) {
        ps[j] = acc[0][j]+acc[1][j]+acc[2][j]+acc[3][j];
        pq[j] = acc[0][j]*acc[0][j]+acc[1][j]*acc[1][j]+acc[2][j]*acc[2][j]+acc[3][j]*acc[3][j];
    }
    #pragma unroll
    for (int j = 0; j < 7; j++) red[ty*112 + tx*7 + j] = ps[j];
    __syncthreads();
    if (t < 112) {
        float s = 0.f;
        #pragma unroll
        for (int yy = 0; yy < 16; yy++) s += red[yy*112 + t];
        g_part[blockIdx.x*224 + t] = s;
    }
    __syncthreads();
    #pragma unroll
    for (int j = 0; j < 7; j++) red[ty*112 + tx*7 + j] = pq[j];
    __syncthreads();
    if (t < 112) {
        float s = 0.f;
        #pragma unroll
        for (int yy = 0; yy < 16; yy++) s += red[yy*112 + t];
        g_part[blockIdx.x*224 + 112 + t] = s;
    }
}

// ---------------- K2: reduce BN partials -> affine -------------------------
__global__ void k_affine(const float* __restrict__ gq, const float* __restrict__ bq,
                         const float* __restrict__ gv, const float* __restrict__ bv) {
    int t = threadIdx.x;
    if (t >= 112 || (t >= 64 && t < 80)) return;
    float s = 0.f, s2 = 0.f;
    for (int i = 0; i < 288; i++) {
        s  += g_part[i*224 + t];
        s2 += g_part[i*224 + 112 + t];
    }
    float mu  = s / (float)NROW;
    float var = s2 / (float)NROW - mu*mu;
    if (t < 64) {
        float sc = gq[t] * rsqrtf(var + 1e-5f);
        g_qaff[t] = sc; g_qaff[64+t] = bq[t] - mu*sc;
    } else {
        int c = t - 80;
        float sc = gv[c] * rsqrtf(var + 1e-5f);
        g_vaff[c] = sc; g_vaff[32+c] = bv[c] - mu*sc;
    }
}

// ---------------- K3b: BN(V) -> fp32 [m][col] + fp16 [col][m] -------------
__global__ void k_vt() {
    __shared__ unsigned short sh[64][33];
    int t = threadIdx.x;
    int cg = blockIdx.x & 3, mg = blockIdx.x >> 2;   // 4 x 72
    int col0 = cg*64, m0 = mg*32;
    for (int e = t; e < 2048; e += 256) {
        int lm = e >> 6, lc = e & 63;
        int col = col0 + lc;
        int b = col >> 5, v = col & 31;
        int m = m0 + lm;
        float xv = g_v[((size_t)b*NTOK + m)*32 + v] * g_vaff[v] + g_vaff[32+v];
        g_vt[(size_t)m*256 + col] = xv;
        sh[lc][lm] = __half_as_ushort(__float2half_rn(xv));
    }
    __syncthreads();
    int lc = t >> 2, sub = t & 3;
    uint32_t w[4];
    #pragma unroll
    for (int j = 0; j < 4; j++)
        w[j] = (uint32_t)sh[lc][sub*8 + 2*j] | ((uint32_t)sh[lc][sub*8 + 2*j+1] << 16);
    *(uint4*)(g_vthf + (size_t)(col0 + lc)*NTOK + m0 + sub*8) = make_uint4(w[0], w[1], w[2], w[3]);
}

// ---------------- K5: BIG GEMM, fragment-pipelined HMMA -------------------
#define TK    64
#define NCH   (GK/TK)      // 36
#define AOFF  0
#define BOFF  16384
#define STG   32768
#define SMEM_MMA (2*STG)   // 65536

__global__ void __launch_bounds__(256, 2) k_lamp_hmma() {
    extern __shared__ char smem[];
    uint32_t sb = smem_u32(smem);
    int t = threadIdx.x;
    int nbase = blockIdx.y * 8;
    int col0  = blockIdx.x * 128;

    int n_loc = t >> 5, mi2 = t & 31;
    int n = nbase + n_loc;
    int n_row = n / 48, n_col = n - n_row*48;

    int wid = t >> 5, lane = t & 31;
    int wm = wid >> 1, wn = wid & 1;
    int lr = lane & 15, lc2 = (lane >> 4) * 16;

    float acc[2][8][4];
    #pragma unroll
    for (int i = 0; i < 2; i++)
        #pragma unroll
        for (int j = 0; j < 8; j++)
            #pragma unroll
            for (int q = 0; q < 4; q++) acc[i][j][q] = 0.f;

    uint4 ra0, ra1, rb0, rb1;

    auto ldgA = [&](int c) {
        int ma = c*TK + 2*mi2;
        int mr = ma / 48, mc2 = ma - mr*48;
        const uint4* pa = (const uint4*)(g_Rh + (size_t)((mr - n_row + 47)*95 + (mc2 - n_col + 47)) * 16);
        ra0 = pa[0]; ra1 = pa[1];
        int mb = ma + 1;
        mr = mb / 48; mc2 = mb - mr*48;
        const uint4* pb = (const uint4*)(g_Rh + (size_t)((mr - n_row + 47)*95 + (mc2 - n_col + 47)) * 16);
        rb0 = pb[0]; rb1 = pb[1];
    };
    auto stsA = [&](int p) {
        char* base = smem + p*STG + AOFF;
        uint32_t aw[8] = {ra0.x,ra0.y,ra0.z,ra0.w,ra1.x,ra1.y,ra1.z,ra1.w};
        uint32_t bw[8] = {rb0.x,rb0.y,rb0.z,rb0.w,rb1.x,rb1.y,rb1.z,rb1.w};
        uint32_t cb = (uint32_t)mi2 * 4;
        #pragma unroll
        for (int i = 0; i < 8; i++) {
            uint32_t w0 = __byte_perm(aw[i], bw[i], 0x5410);
            uint32_t w1 = __byte_perm(aw[i], bw[i], 0x7632);
            uint32_t r0 = (uint32_t)(n_loc*16 + 2*i);
            uint32_t r1 = r0 + 1;
            *(uint32_t*)(base + ((r0*128u + cb) ^ ((r0 & 7u) << 4))) = w0;
            *(uint32_t*)(base + ((r1*128u + cb) ^ ((r1 & 7u) << 4))) = w1;
        }
    };
    auto cpB = [&](int c, int p) {
        int m0 = c * TK;
        uint32_t sa = sb + p*STG + BOFF;
        #pragma unroll
        for (int i = 0; i < 4; i++) {
            int idx = t*4 + i;
            uint32_t col = (uint32_t)(idx >> 3), ch = (uint32_t)(idx & 7);
            uint32_t off = (col*128u + ch*16u) ^ ((col & 7u) << 4);
            cp16(sa + off, g_vthf + (size_t)(col0 + col)*NTOK + m0 + ch*8);
        }
    };

    // fragment-load helpers (kk, ng compile-time under full unroll)
    auto aAddr = [&](uint32_t sa, int kk, int mf) {
        uint32_t row = (uint32_t)(wm*32 + mf*16 + lr);
        return sa + AOFF + ((row*128u + (uint32_t)(kk*32) + (uint32_t)lc2) ^ ((row & 7u) << 4));
    };
    auto bAddr = [&](uint32_t sa, int kk, int ng) {
        uint32_t row = (uint32_t)(wn*64 + ng*16 + lr);
        return sa + BOFF + ((row*128u + (uint32_t)(kk*32) + (uint32_t)lc2) ^ ((row & 7u) << 4));
    };

    // prologue
    ldgA(0); cpB(0, 0); CP_COMMIT(); stsA(0);
    ldgA(1); cpB(1, 1); CP_COMMIT();
    CP_WAIT1();
    __syncthreads();

    int p = 0;
    for (int c = 0; c < NCH; c++) {
        uint32_t sa = sb + p*STG;
        uint32_t aa[2][8], bb[2][4];
        // preload kk=0 fragments
        ldmx4(aa[0] + 0, aAddr(sa, 0, 0));
        ldmx4(aa[0] + 4, aAddr(sa, 0, 1));
        ldmx4(bb[0], bAddr(sa, 0, 0));
        #pragma unroll
        for (int kk = 0; kk < 4; kk++) {
            int ca = kk & 1;
            #pragma unroll
            for (int ng = 0; ng < 4; ng++) {
                int pb = (kk*4 + ng) & 1;
                // prefetch next fragment group
                if (ng < 3) {
                    ldmx4(bb[pb^1], bAddr(sa, kk, ng + 1));
                } else if (kk < 3) {
                    ldmx4(aa[ca^1] + 0, aAddr(sa, kk + 1, 0));
                    ldmx4(aa[ca^1] + 4, aAddr(sa, kk + 1, 1));
                    ldmx4(bb[pb^1], bAddr(sa, kk + 1, 0));
                }
                // 4 MMAs on current group
                #pragma unroll
                for (int mf = 0; mf < 2; mf++)
                    #pragma unroll
                    for (int j = 0; j < 2; j++)
                        mma16816(acc[mf][2*ng + j], aa[ca] + mf*4, bb[pb][j], bb[pb][j + 2]);
            }
        }
        if (c + 1 < NCH) stsA(1 - p);
        if (c + 2 < NCH) ldgA(c + 2);
        CP_WAIT0();
        __syncthreads();
        if (c + 2 < NCH) { cpB(c + 2, p); CP_COMMIT(); }
        p ^= 1;
    }

    #pragma unroll
    for (int mf = 0; mf < 2; mf++) {
        #pragma unroll
        for (int nf = 0; nf < 8; nf++) {
            int r0 = blockIdx.y*128 + wm*32 + mf*16 + (lane >> 2);
            int c0 = col0 + wn*64 + nf*8 + (lane & 3)*2;
            *(float2*)&g_lamp[(size_t)r0*256 + c0]     = make_float2(acc[mf][nf][0], acc[mf][nf][1]);
            *(float2*)&g_lamp[(size_t)(r0+8)*256 + c0] = make_float2(acc[mf][nf][2], acc[mf][nf][3]);
        }
    }
}

// ---------------- K3: softmax over m ---------------------------------------
__global__ void k_softmax() {
    __shared__ float red[256];
    int bk = blockIdx.x, t = threadIdx.x;
    const float* src = g_kT + (size_t)bk*NTOK;
    float r[9];
    #pragma unroll
    for (int i = 0; i < 9; i++) r[i] = src[t + i*256];
    float mx = r[0];
    #pragma unroll
    for (int i = 1; i < 9; i++) mx = fmaxf(mx, r[i]);
    red[t] = mx; __syncthreads();
    for (int s = 128; s > 0; s >>= 1) { if (t < s) red[t] = fmaxf(red[t], red[t+s]); __syncthreads(); }
    mx = red[0]; __syncthreads();
    float sum = 0.f;
    #pragma unroll
    for (int i = 0; i < 9; i++) { r[i] = expf(r[i] - mx); sum += r[i]; }
    red[t] = sum; __syncthreads();
    for (int s = 128; s > 0; s >>= 1) { if (t < s) red[t] += red[t+s]; __syncthreads(); }
    float inv = 1.0f / red[0];
    float* dst = g_ksm + (size_t)bk*NTOK;
    #pragma unroll
    for (int i = 0; i < 9; i++) dst[t + i*256] = r[i] * inv;
}

// ---------------- K4: content lambda lamc ---------------------------------
__global__ void k_lamc_part() {
    __shared__ float Ks[16*128];
    __shared__ float Vs[128*32];
    int b = blockIdx.x / 18, mc = blockIdx.x - b*18;
    int m0 = mc * 128;
    int t = threadIdx.x;
    for (int i = t; i < 2048; i += 512) { int k = i>>7, mm = i&127; Ks[i] = g_ksm[(size_t)(b*16+k)*NTOK + m0+mm]; }
    for (int i = t; i < 4096; i += 512) { int mm = i>>5, v = i&31;  Vs[i] = g_vt[(size_t)(m0+mm)*256 + b*32 + v]; }
    __syncthreads();
    int k = t >> 5, v = t & 31;
    float acc = 0.f;
    #pragma unroll 8
    for (int mm = 0; mm < 128; mm++) acc += Ks[k*128+mm] * Vs[mm*32+v];
    g_lamc_part[(size_t)blockIdx.x*512 + t] = acc;
}
__global__ void k_lamc_red() {
    int b = blockIdx.x, t = threadIdx.x;
    float s = 0.f;
    for (int mc = 0; mc < 18; mc++) s += g_lamc_part[(size_t)(b*18+mc)*512 + t];
    g_lamc[b*512 + t] = s;
}

// ---------------- K6: fused consumers (app + mot, warp-per-row) -----------
__global__ void __launch_bounds__(256) k_out(const float* __restrict__ cor,
                       const float* __restrict__ Wce, const float* __restrict__ bce,
                       const float* __restrict__ Wcc, const float* __restrict__ Wmp,
                       const float* __restrict__ bmp,
                       float* __restrict__ app, float* __restrict__ mot) {
    __shared__ float WccS[64*129];   // [o][c] padded
    __shared__ float WmpS[128*65];   // [o][c] padded
    __shared__ float WceS[128];
    __shared__ float bceS[64];
    __shared__ float bmpS[128];
    __shared__ float lamcS[512];
    int t = threadIdx.x;
    int b = blockIdx.x / 288;        // 288 blocks per batch (8 rows each)

    for (int i = t; i < 8192; i += 256) WccS[(i>>7)*129 + (i&127)] = Wcc[i];
    for (int i = t; i < 8192; i += 256) WmpS[(i>>6)*65 + (i&63)]   = Wmp[i];
    if (t < 128) WceS[t] = Wce[t];
    if (t < 64)  bceS[t] = bce[t];
    if (t < 128) bmpS[t] = bmp[t];
    for (int i = t; i < 512; i += 256) lamcS[i] = g_lamc[b*512 + i];
    __syncthreads();

    int w = t >> 5, lane = t & 31;
    int row = blockIdx.x*8 + w;
    int n = row - b*NTOK;

    float q0 = g_q[(size_t)row*64 + lane]      * g_qaff[lane]    + g_qaff[64+lane];
    float q1 = g_q[(size_t)row*64 + 32 + lane] * g_qaff[32+lane] + g_qaff[96+lane];
    float c0 = cor[(size_t)row*2], c1 = cor[(size_t)row*2 + 1];
    float ce0 = c0*WceS[lane*2]      + c1*WceS[lane*2+1]      + bceS[lane];
    float ce1 = c0*WceS[(32+lane)*2] + c1*WceS[(32+lane)*2+1] + bceS[32+lane];

    float y[4] = {0.f,0.f,0.f,0.f}, cr[4] = {0.f,0.f,0.f,0.f};
    const float* lp = g_lamp + (size_t)(n*16)*256 + b*32 + lane;
    #pragma unroll
    for (int k = 0; k < 16; k++) {
        float l = lp[(size_t)k*256] + lamcS[k*32 + lane];
        y[0]  += __shfl_sync(0xffffffffu, q0, k)      * l;
        y[1]  += __shfl_sync(0xffffffffu, q0, 16 + k) * l;
        y[2]  += __shfl_sync(0xffffffffu, q1, k)      * l;
        y[3]  += __shfl_sync(0xffffffffu, q1, 16 + k) * l;
        cr[0] += __shfl_sync(0xffffffffu, ce0, k)      * l;
        cr[1] += __shfl_sync(0xffffffffu, ce0, 16 + k) * l;
        cr[2] += __shfl_sync(0xffffffffu, ce1, k)      * l;
        cr[3] += __shfl_sync(0xffffffffu, ce1, 16 + k) * l;
    }
    #pragma unroll
    for (int h = 0; h < 4; h++)
        app[(size_t)row*128 + h*32 + lane] = y[h];

    // dif[o] = sum_c crow[c]*Wcc[o][c] - ce[o]
    float d0 = -ce0, d1 = -ce1;
    #pragma unroll 4
    for (int c = 0; c < 128; c++) {
        float crc = __shfl_sync(0xffffffffu, cr[c >> 5], c & 31);
        d0 += crc * WccS[lane*129 + c];
        d1 += crc * WccS[(32+lane)*129 + c];
    }

    // mot = dif * Wmp^T + bmp (warp-local via shfl)
    float m[4] = {bmpS[lane], bmpS[32+lane], bmpS[64+lane], bmpS[96+lane]};
    #pragma unroll 8
    for (int c = 0; c < 32; c++) {
        float dc = __shfl_sync(0xffffffffu, d0, c);
        #pragma unroll
        for (int h = 0; h < 4; h++) m[h] += dc * WmpS[(h*32+lane)*65 + c];
    }
    #pragma unroll 8
    for (int c = 0; c < 32; c++) {
        float dc = __shfl_sync(0xffffffffu, d1, c);
        #pragma unroll
        for (int h = 0; h < 4; h++) m[h] += dc * WmpS[(h*32+lane)*65 + 32 + c];
    }
    #pragma unroll
    for (int h = 0; h < 4; h++)
        mot[(size_t)row*128 + h*32 + lane] = m[h];
}

// ---------------- launch ---------------------------------------------------
extern "C" void kernel_launch(void* const* d_in, const int* in_sizes, int n_in,
                              void* d_out, int out_size) {
    const float* x   = (const float*)d_in[0];
    const float* cor = (const float*)d_in[1];
    const float* Wq  = (const float*)d_in[2];
    const float* Wk  = (const float*)d_in[3];
    const float* Wv  = (const float*)d_in[4];
    const float* Wce = (const float*)d_in[5];
    const float* bce = (const float*)d_in[6];
    const float* Wcc = (const float*)d_in[7];
    const float* Wmp = (const float*)d_in[8];
    const float* bmp = (const float*)d_in[9];
    const float* gq  = (const float*)d_in[10];
    const float* bq  = (const float*)d_in[11];
    const float* gv  = (const float*)d_in[12];
    const float* bv  = (const float*)d_in[13];
    const float* rpe = (const float*)d_in[14];
    float* app = (float*)d_out;
    float* mot = app + (size_t)NROW*128;

    cudaFuncSetAttribute(k_lamp_hmma, cudaFuncAttributeMaxDynamicSharedMemorySize, SMEM_MMA);

    k_proj<<<288 + (RTAB + 255)/256, 256>>>(x, Wq, Wk, Wv, rpe);  // #1
    k_affine<<<1, 128>>>(gq, bq, gv, bv);                          // #2
    k_vt<<<288, 256>>>();                                          // #3
    k_lamp_hmma<<<dim3(2, 288), 256, SMEM_MMA>>>();                // #4 <- profiled
    k_softmax<<<128, 256>>>();                                     // #5
    k_lamc_part<<<144, 512>>>();                                   // #6
    k_lamc_red<<<8, 512>>>();                                      // #7
    k_out<<<NROW/8, 256>>>(cor, Wce, bce, Wcc, Wmp, bmp, app, mot); // #8
}

// round 12
// speedup vs baseline: 1.3421x; 1.0140x over previous
#include <cuda_runtime.h>
#include <cuda_fp16.h>
#include <math.h>
#include <stdint.h>

#define B_    8
#define NTOK  2304
#define NROW  (B_*NTOK)      // 18432
#define HK    64
#define KD    16
#define VD    32
#define GM    (NTOK*KD)      // 36864
#define GN    (B_*VD)        // 256
#define GK    NTOK           // 2304
#define RTAB  (95*95*16)     // 144400

// ---------------- scratch (device globals; no allocations) ----------------
__device__ __align__(256) float g_q[(size_t)NROW*HK];
__device__ __align__(256) float g_kT[(size_t)B_*KD*NTOK];
__device__ __align__(256) float g_v[(size_t)NROW*VD];
__device__ __align__(256) float g_ksm[(size_t)B_*KD*NTOK];
__device__ __align__(256) float g_vt[(size_t)NTOK*GN];
__device__ __align__(256) unsigned short g_vthf[(size_t)GN*NTOK];      // [(b,v)][m] fp16
__device__ __align__(256) unsigned short g_Rh[RTAB];                   // rel-pos fp16
__device__ __align__(256) float g_part[288*224];
__device__ __align__(256) float g_lamc_part[(size_t)144*KD*VD];
__device__ __align__(256) float g_lamc[(size_t)B_*KD*VD];
__device__ __align__(256) float g_qaff[2*HK];
__device__ __align__(256) float g_vaff[2*VD];
__device__ __align__(256) float g_lamp[(size_t)GM*GN];

// ---------------- portable PTX helpers ------------------------------------
__device__ __forceinline__ uint32_t smem_u32(const void* p) {
    uint32_t a;
    asm("{ .reg .u64 t; cvta.to.shared.u64 t, %1; cvt.u32.u64 %0, t; }" : "=r"(a) : "l"(p));
    return a;
}
__device__ __forceinline__ void ldmx4(uint32_t* r, uint32_t addr) {
    asm volatile("ldmatrix.sync.aligned.m8n8.x4.shared.b16 {%0,%1,%2,%3}, [%4];"
        : "=r"(r[0]), "=r"(r[1]), "=r"(r[2]), "=r"(r[3]) : "r"(addr));
}
__device__ __forceinline__ void mma16816(float* d, const uint32_t* a, uint32_t b0, uint32_t b1) {
    asm volatile("mma.sync.aligned.m16n8k16.row.col.f32.f16.f16.f32 "
        "{%0,%1,%2,%3}, {%4,%5,%6,%7}, {%8,%9}, {%0,%1,%2,%3};"
        : "+f"(d[0]), "+f"(d[1]), "+f"(d[2]), "+f"(d[3])
        : "r"(a[0]), "r"(a[1]), "r"(a[2]), "r"(a[3]), "r"(b0), "r"(b1));
}
__device__ __forceinline__ void cp16(uint32_t saddr, const void* g) {
    asm volatile("cp.async.cg.shared.global [%0], [%1], 16;" :: "r"(saddr), "l"(g));
}
#define CP_COMMIT() asm volatile("cp.async.commit_group;" ::: "memory")
#define CP_WAIT1()  asm volatile("cp.async.wait_group 1;" ::: "memory")
#define CP_WAIT0()  asm volatile("cp.async.wait_group 0;" ::: "memory")

// ---------------- K1: q/k/v 1x1 conv + BN partials + R convert ------------
__global__ void __launch_bounds__(256) k_proj(const float* __restrict__ x,
                       const float* __restrict__ Wq,
                       const float* __restrict__ Wk,
                       const float* __restrict__ Wv,
                       const float* __restrict__ R) {
    if (blockIdx.x >= 288) {
        int i = (blockIdx.x - 288)*256 + threadIdx.x;
        if (i < RTAB) g_Rh[i] = __half_as_ushort(__float2half_rn(R[i]));
        return;
    }
    __shared__ float Xs[64*33];
    __shared__ float Ws2[112*33];
    __shared__ float red[16*112];
    int t = threadIdx.x;
    int ty = t >> 4, tx = t & 15;
    int row0 = blockIdx.x * 64;
    int bs = blockIdx.x / 36;
    float acc[4][7];
    #pragma unroll
    for (int i = 0; i < 4; i++)
        #pragma unroll
        for (int j = 0; j < 7; j++) acc[i][j] = 0.f;

    for (int k0 = 0; k0 < 128; k0 += 32) {
        for (int e = t; e < 2048; e += 256) {
            int r = e >> 5, k = e & 31;
            Xs[r*33 + k] = x[(size_t)(row0+r)*128 + k0 + k];
        }
        for (int e = t; e < 3584; e += 256) {
            int o = e >> 5, k = e & 31;
            float w;
            if (o < 64)      w = Wq[o*128 + k0 + k];
            else if (o < 80) w = Wk[(o-64)*128 + k0 + k];
            else             w = Wv[(o-80)*128 + k0 + k];
            Ws2[o*33 + k] = w;
        }
        __syncthreads();
        #pragma unroll 8
        for (int kk = 0; kk < 32; kk++) {
            float a[4], b[7];
            #pragma unroll
            for (int i = 0; i < 4; i++) a[i] = Xs[(ty*4+i)*33 + kk];
            #pragma unroll
            for (int j = 0; j < 7; j++) b[j] = Ws2[(tx*7+j)*33 + kk];
            #pragma unroll
            for (int i = 0; i < 4; i++)
                #pragma unroll
                for (int j = 0; j < 7; j++) acc[i][j] += a[i]*b[j];
        }
        __syncthreads();
    }

    int db = (bs + 4) & 7;
    #pragma unroll
    for (int i = 0; i < 4; i++) {
        int row = row0 + ty*4 + i;
        int n = row - bs*NTOK;
        #pragma unroll
        for (int j = 0; j < 7; j++) {
            int o = tx*7 + j;
            float val = acc[i][j];
            if (o < 64)       g_q[(size_t)row*64 + o] = val;
            else if (o < 80)  g_kT[(size_t)(db*16 + o-64)*NTOK + n] = val;
            else              g_v[((size_t)db*NTOK + n)*32 + (o-80)] = val;
        }
    }
    float ps[7], pq[7];
    #pragma unroll
    for (int j = 0; j < 7; j++) {
        ps[j] = acc[0][j]+acc[1][j]+acc[2][j]+acc[3][j];
        pq[j] = acc[0][j]*acc[0][j]+acc[1][j]*acc[1][j]+acc[2][j]*acc[2][j]+acc[3][j]*acc[3][j];
    }
    #pragma unroll
    for (int j = 0; j < 7; j++) red[ty*112 + tx*7 + j] = ps[j];
    __syncthreads();
    if (t < 112) {
        float s = 0.f;
        #pragma unroll
        for (int yy = 0; yy < 16; yy++) s += red[yy*112 + t];
        g_part[blockIdx.x*224 + t] = s;
    }
    __syncthreads();
    #pragma unroll
    for (int j = 0; j < 7; j++) red[ty*112 + tx*7 + j] = pq[j];
    __syncthreads();
    if (t < 112) {
        float s = 0.f;
        #pragma unroll
        for (int yy = 0; yy < 16; yy++) s += red[yy*112 + t];
        g_part[blockIdx.x*224 + 112 + t] = s;
    }
}

// ---------------- K2: reduce BN partials -> affine (parallel) --------------
__global__ void __launch_bounds__(1024) k_affine(const float* __restrict__ gq,
                         const float* __restrict__ bq,
                         const float* __restrict__ gv, const float* __restrict__ bv) {
    __shared__ float s1[8][112], s2[8][112];
    int t = threadIdx.x;
    int grp = t >> 7, ch = t & 127;
    if (ch < 112) {
        float a = 0.f, b2 = 0.f;
        int i0 = grp*36;
        for (int i = i0; i < i0 + 36; i++) {
            a  += g_part[i*224 + ch];
            b2 += g_part[i*224 + 112 + ch];
        }
        s1[grp][ch] = a; s2[grp][ch] = b2;
    }
    __syncthreads();
    if (grp == 0 && ch < 112 && !(ch >= 64 && ch < 80)) {
        float s = 0.f, ss = 0.f;
        #pragma unroll
        for (int g = 0; g < 8; g++) { s += s1[g][ch]; ss += s2[g][ch]; }
        float mu  = s / (float)NROW;
        float var = ss / (float)NROW - mu*mu;
        if (ch < 64) {
            float sc = gq[ch] * rsqrtf(var + 1e-5f);
            g_qaff[ch] = sc; g_qaff[64+ch] = bq[ch] - mu*sc;
        } else {
            int c = ch - 80;
            float sc = gv[c] * rsqrtf(var + 1e-5f);
            g_vaff[c] = sc; g_vaff[32+c] = bv[c] - mu*sc;
        }
    }
}

// ---------------- K3: vt + softmax merged ----------------------------------
__global__ void __launch_bounds__(256) k_vtsoft() {
    __shared__ unsigned short sh[64][33];
    __shared__ float red[256];
    int t = threadIdx.x;
    if (blockIdx.x < 288) {
        int cg = blockIdx.x & 3, mg = blockIdx.x >> 2;   // 4 x 72
        int col0 = cg*64, m0 = mg*32;
        for (int e = t; e < 2048; e += 256) {
            int lm = e >> 6, lc = e & 63;
            int col = col0 + lc;
            int b = col >> 5, v = col & 31;
            int m = m0 + lm;
            float xv = g_v[((size_t)b*NTOK + m)*32 + v] * g_vaff[v] + g_vaff[32+v];
            g_vt[(size_t)m*256 + col] = xv;
            sh[lc][lm] = __half_as_ushort(__float2half_rn(xv));
        }
        __syncthreads();
        int lc = t >> 2, sub = t & 3;
        uint32_t w[4];
        #pragma unroll
        for (int j = 0; j < 4; j++)
            w[j] = (uint32_t)sh[lc][sub*8 + 2*j] | ((uint32_t)sh[lc][sub*8 + 2*j+1] << 16);
        *(uint4*)(g_vthf + (size_t)(col0 + lc)*NTOK + m0 + sub*8) = make_uint4(w[0], w[1], w[2], w[3]);
    } else {
        int bk = blockIdx.x - 288;
        const float* src = g_kT + (size_t)bk*NTOK;
        float r[9];
        #pragma unroll
        for (int i = 0; i < 9; i++) r[i] = src[t + i*256];
        float mx = r[0];
        #pragma unroll
        for (int i = 1; i < 9; i++) mx = fmaxf(mx, r[i]);
        red[t] = mx; __syncthreads();
        for (int s = 128; s > 0; s >>= 1) { if (t < s) red[t] = fmaxf(red[t], red[t+s]); __syncthreads(); }
        mx = red[0]; __syncthreads();
        float sum = 0.f;
        #pragma unroll
        for (int i = 0; i < 9; i++) { r[i] = expf(r[i] - mx); sum += r[i]; }
        red[t] = sum; __syncthreads();
        for (int s = 128; s > 0; s >>= 1) { if (t < s) red[t] += red[t+s]; __syncthreads(); }
        float inv = 1.0f / red[0];
        float* dst = g_ksm + (size_t)bk*NTOK;
        #pragma unroll
        for (int i = 0; i < 9; i++) dst[t + i*256] = r[i] * inv;
    }
}

// ---------------- K5: BIG GEMM, 16 warps x 32x32 tile, 2 CTAs/SM ----------
#define TK    64
#define NCH   (GK/TK)      // 36
#define AOFF  0
#define BOFF  16384
#define STG   32768
#define SMEM_MMA (2*STG)   // 65536

__global__ void __launch_bounds__(512, 2) k_lamp_hmma() {
    extern __shared__ char smem[];
    uint32_t sb = smem_u32(smem);
    int t = threadIdx.x;
    int nbase = blockIdx.y * 8;
    int col0  = blockIdx.x * 128;

    // A-gather role: one m per thread, all 16 k
    int n_loc = t >> 6, mi = t & 63;
    int n = nbase + n_loc;
    int n_row = n / 48, n_col = n - n_row*48;
    bool even = !(t & 1);

    // compute role: 16 warps, 4x4, warp tile 32x32
    int wid = t >> 5, lane = t & 31;
    int wm = wid >> 2, wn = wid & 3;
    int lr = lane & 15, lc2 = (lane >> 4) * 16;

    float acc[2][4][4];
    #pragma unroll
    for (int i = 0; i < 2; i++)
        #pragma unroll
        for (int j = 0; j < 4; j++)
            #pragma unroll
            for (int q = 0; q < 4; q++) acc[i][j][q] = 0.f;

    auto aAddr = [&](uint32_t sa, int kk, int mf) {
        uint32_t row = (uint32_t)(wm*32 + mf*16 + lr);
        return sa + AOFF + ((row*128u + (uint32_t)(kk*32) + (uint32_t)lc2) ^ ((row & 7u) << 4));
    };
    auto bAddr = [&](uint32_t sa, int kk, int ng) {
        uint32_t row = (uint32_t)(wn*32 + ng*16 + lr);
        return sa + BOFF + ((row*128u + (uint32_t)(kk*32) + (uint32_t)lc2) ^ ((row & 7u) << 4));
    };

    // gather+store A for chunk c into stage p (LDG then shfl-pack then STS)
    auto gatherA = [&](int c, int p) {
        int m = c*TK + mi;
        int mr = m / 48, mc2 = m - mr*48;
        const uint4* pr = (const uint4*)(g_Rh + (size_t)((mr - n_row + 47)*95 + (mc2 - n_col + 47)) * 16);
        uint4 h0 = pr[0], h1 = pr[1];
        char* base = smem + p*STG + AOFF;
        uint32_t rr[8] = {h0.x,h0.y,h0.z,h0.w,h1.x,h1.y,h1.z,h1.w};
        uint32_t cb = (uint32_t)(mi & 62) * 2;
        #pragma unroll
        for (int j = 0; j < 8; j++) {
            uint32_t got = __shfl_xor_sync(0xffffffffu, rr[j], 1);
            uint32_t a = even ? rr[j] : got;   // m-even data (k pair 2j,2j+1)
            uint32_t b = even ? got   : rr[j]; // m-odd data
            if (even) {
                uint32_t w0 = __byte_perm(a, b, 0x5410);    // k = 2j
                uint32_t r0 = (uint32_t)(n_loc*16 + 2*j);
                *(uint32_t*)(base + ((r0*128u + cb) ^ ((r0 & 7u) << 4))) = w0;
            } else {
                uint32_t w1 = __byte_perm(a, b, 0x7632);    // k = 2j+1
                uint32_t r1 = (uint32_t)(n_loc*16 + 2*j + 1);
                *(uint32_t*)(base + ((r1*128u + cb) ^ ((r1 & 7u) << 4))) = w1;
            }
        }
    };
    auto cpB = [&](int c, int p) {
        int m0 = c * TK;
        uint32_t sa = sb + p*STG + BOFF;
        #pragma unroll
        for (int i = 0; i < 2; i++) {
            int idx = t*2 + i;                 // 1024 = 128 cols x 8 chunks
            uint32_t col = (uint32_t)(idx >> 3), ch = (uint32_t)(idx & 7);
            uint32_t off = (col*128u + ch*16u) ^ ((col & 7u) << 4);
            cp16(sa + off, g_vthf + (size_t)(col0 + col)*NTOK + m0 + ch*8);
        }
    };

    // prologue
    gatherA(0, 0);
    cpB(0, 0); CP_COMMIT();
    cpB(1, 1); CP_COMMIT();
    CP_WAIT1();
    __syncthreads();

    int p = 0;
    for (int c = 0; c < NCH; c++) {
        uint32_t sa = sb + p*STG;
        #pragma unroll
        for (int kk = 0; kk < 4; kk++) {
            uint32_t aa[2][4], bb[2][4];
            ldmx4(aa[0], aAddr(sa, kk, 0));
            ldmx4(aa[1], aAddr(sa, kk, 1));
            ldmx4(bb[0], bAddr(sa, kk, 0));
            ldmx4(bb[1], bAddr(sa, kk, 1));
            #pragma unroll
            for (int mf = 0; mf < 2; mf++)
                #pragma unroll
                for (int ng = 0; ng < 2; ng++)
                    #pragma unroll
                    for (int j = 0; j < 2; j++)
                        mma16816(acc[mf][ng*2 + j], aa[mf], bb[ng][j], bb[ng][j + 2]);
        }
        if (c + 1 < NCH) gatherA(c + 1, 1 - p);   // stage (1-p) A consumed in chunk c-1
        CP_WAIT0();                                // B(c+1) complete
        __syncthreads();
        if (c + 2 < NCH) { cpB(c + 2, p); CP_COMMIT(); }
        p ^= 1;
    }

    // epilogue
    #pragma unroll
    for (int mf = 0; mf < 2; mf++) {
        #pragma unroll
        for (int nf = 0; nf < 4; nf++) {
            int r0 = blockIdx.y*128 + wm*32 + mf*16 + (lane >> 2);
            int c0 = col0 + wn*32 + nf*8 + (lane & 3)*2;
            *(float2*)&g_lamp[(size_t)r0*256 + c0]     = make_float2(acc[mf][nf][0], acc[mf][nf][1]);
            *(float2*)&g_lamp[(size_t)(r0+8)*256 + c0] = make_float2(acc[mf][nf][2], acc[mf][nf][3]);
        }
    }
}

// ---------------- K4: content lambda lamc ---------------------------------
__global__ void k_lamc_part() {
    __shared__ float Ks[16*128];
    __shared__ float Vs[128*32];
    int b = blockIdx.x / 18, mc = blockIdx.x - b*18;
    int m0 = mc * 128;
    int t = threadIdx.x;
    for (int i = t; i < 2048; i += 512) { int k = i>>7, mm = i&127; Ks[i] = g_ksm[(size_t)(b*16+k)*NTOK + m0+mm]; }
    for (int i = t; i < 4096; i += 512) { int mm = i>>5, v = i&31;  Vs[i] = g_vt[(size_t)(m0+mm)*256 + b*32 + v]; }
    __syncthreads();
    int k = t >> 5, v = t & 31;
    float acc = 0.f;
    #pragma unroll 8
    for (int mm = 0; mm < 128; mm++) acc += Ks[k*128+mm] * Vs[mm*32+v];
    g_lamc_part[(size_t)blockIdx.x*512 + t] = acc;
}
__global__ void k_lamc_red() {
    int b = blockIdx.x, t = threadIdx.x;
    float s = 0.f;
    for (int mc = 0; mc < 18; mc++) s += g_lamc_part[(size_t)(b*18+mc)*512 + t];
    g_lamc[b*512 + t] = s;
}

// ---------------- K6: fused consumers (32 rows/block, warp-per-row) -------
__global__ void __launch_bounds__(256) k_out(const float* __restrict__ cor,
                       const float* __restrict__ Wce, const float* __restrict__ bce,
                       const float* __restrict__ Wcc, const float* __restrict__ Wmp,
                       const float* __restrict__ bmp,
                       float* __restrict__ app, float* __restrict__ mot) {
    __shared__ float WccS[64*129];   // [o][c] padded
    __shared__ float WmpS[128*65];   // [o][c] padded
    __shared__ float WceS[128];
    __shared__ float bceS[64];
    __shared__ float bmpS[128];
    __shared__ float lamcS[512];
    int t = threadIdx.x;
    int b = blockIdx.x / 72;         // 72 blocks per batch (32 rows each)

    for (int i = t; i < 8192; i += 256) WccS[(i>>7)*129 + (i&127)] = Wcc[i];
    for (int i = t; i < 8192; i += 256) WmpS[(i>>6)*65 + (i&63)]   = Wmp[i];
    if (t < 128) WceS[t] = Wce[t];
    if (t < 64)  bceS[t] = bce[t];
    if (t < 128) bmpS[t] = bmp[t];
    for (int i = t; i < 512; i += 256) lamcS[i] = g_lamc[b*512 + i];
    __syncthreads();

    int w = t >> 5, lane = t & 31;
    for (int it = 0; it < 4; it++) {
        int row = blockIdx.x*32 + it*8 + w;
        int n = row - b*NTOK;

        float q0 = g_q[(size_t)row*64 + lane]      * g_qaff[lane]    + g_qaff[64+lane];
        float q1 = g_q[(size_t)row*64 + 32 + lane] * g_qaff[32+lane] + g_qaff[96+lane];
        float c0 = cor[(size_t)row*2], c1 = cor[(size_t)row*2 + 1];
        float ce0 = c0*WceS[lane*2]      + c1*WceS[lane*2+1]      + bceS[lane];
        float ce1 = c0*WceS[(32+lane)*2] + c1*WceS[(32+lane)*2+1] + bceS[32+lane];

        float y[4] = {0.f,0.f,0.f,0.f}, cr[4] = {0.f,0.f,0.f,0.f};
        const float* lp = g_lamp + (size_t)(n*16)*256 + b*32 + lane;
        #pragma unroll
        for (int k = 0; k < 16; k++) {
            float l = lp[(size_t)k*256] + lamcS[k*32 + lane];
            y[0]  += __shfl_sync(0xffffffffu, q0, k)      * l;
            y[1]  += __shfl_sync(0xffffffffu, q0, 16 + k) * l;
            y[2]  += __shfl_sync(0xffffffffu, q1, k)      * l;
            y[3]  += __shfl_sync(0xffffffffu, q1, 16 + k) * l;
            cr[0] += __shfl_sync(0xffffffffu, ce0, k)      * l;
            cr[1] += __shfl_sync(0xffffffffu, ce0, 16 + k) * l;
            cr[2] += __shfl_sync(0xffffffffu, ce1, k)      * l;
            cr[3] += __shfl_sync(0xffffffffu, ce1, 16 + k) * l;
        }
        #pragma unroll
        for (int h = 0; h < 4; h++)
            app[(size_t)row*128 + h*32 + lane] = y[h];

        float d0 = -ce0, d1 = -ce1;
        #pragma unroll 4
        for (int c = 0; c < 128; c++) {
            float crc = __shfl_sync(0xffffffffu, cr[c >> 5], c & 31);
            d0 += crc * WccS[lane*129 + c];
            d1 += crc * WccS[(32+lane)*129 + c];
        }

        float m[4] = {bmpS[lane], bmpS[32+lane], bmpS[64+lane], bmpS[96+lane]};
        #pragma unroll 8
        for (int c = 0; c < 32; c++) {
            float dc = __shfl_sync(0xffffffffu, d0, c);
            #pragma unroll
            for (int h = 0; h < 4; h++) m[h] += dc * WmpS[(h*32+lane)*65 + c];
        }
        #pragma unroll 8
        for (int c = 0; c < 32; c++) {
            float dc = __shfl_sync(0xffffffffu, d1, c);
            #pragma unroll
            for (int h = 0; h < 4; h++) m[h] += dc * WmpS[(h*32+lane)*65 + 32 + c];
        }
        #pragma unroll
        for (int h = 0; h < 4; h++)
            mot[(size_t)row*128 + h*32 + lane] = m[h];
    }
}

// ---------------- launch ---------------------------------------------------
extern "C" void kernel_launch(void* const* d_in, const int* in_sizes, int n_in,
                              void* d_out, int out_size) {
    const float* x   = (const float*)d_in[0];
    const float* cor = (const float*)d_in[1];
    const float* Wq  = (const float*)d_in[2];
    const float* Wk  = (const float*)d_in[3];
    const float* Wv  = (const float*)d_in[4];
    const float* Wce = (const float*)d_in[5];
    const float* bce = (const float*)d_in[6];
    const float* Wcc = (const float*)d_in[7];
    const float* Wmp = (const float*)d_in[8];
    const float* bmp = (const float*)d_in[9];
    const float* gq  = (const float*)d_in[10];
    const float* bq  = (const float*)d_in[11];
    const float* gv  = (const float*)d_in[12];
    const float* bv  = (const float*)d_in[13];
    const float* rpe = (const float*)d_in[14];
    float* app = (float*)d_out;
    float* mot = app + (size_t)NROW*128;

    cudaFuncSetAttribute(k_lamp_hmma, cudaFuncAttributeMaxDynamicSharedMemorySize, SMEM_MMA);

    k_proj<<<288 + (RTAB + 255)/256, 256>>>(x, Wq, Wk, Wv, rpe);  // #1
    k_affine<<<1, 1024>>>(gq, bq, gv, bv);                         // #2
    k_vtsoft<<<416, 256>>>();                                      // #3
    k_lamp_hmma<<<dim3(2, 288), 512, SMEM_MMA>>>();                // #4 <- profiled
    k_lamc_part<<<144, 512>>>();                                   // #5
    k_lamc_red<<<8, 512>>>();                                      // #6
    k_out<<<576, 256>>>(cor, Wce, bce, Wcc, Wmp, bmp, app, mot);   // #7
}

// round 13
// speedup vs baseline: 1.4327x; 1.0675x over previous
#include <cuda_runtime.h>
#include <cuda_fp16.h>
#include <math.h>
#include <stdint.h>

#define B_    8
#define NTOK  2304
#define NROW  (B_*NTOK)      // 18432
#define HK    64
#define KD    16
#define VD    32
#define GM    (NTOK*KD)      // 36864
#define GN    (B_*VD)        // 256
#define GK    NTOK           // 2304
#define RTAB  (95*95*16)     // 144400

// ---------------- scratch (device globals; no allocations) ----------------
__device__ __align__(256) float g_q[(size_t)NROW*HK];
__device__ __align__(256) float g_kT[(size_t)B_*KD*NTOK];
__device__ __align__(256) float g_v[(size_t)NROW*VD];
__device__ __align__(256) float g_ksm[(size_t)B_*KD*NTOK];
__device__ __align__(256) float g_vt[(size_t)NTOK*GN];
__device__ __align__(256) unsigned short g_vthf[(size_t)GN*NTOK];      // [(b,v)][m] fp16
__device__ __align__(256) unsigned short g_Rh[RTAB];                   // rel-pos fp16
__device__ __align__(256) float g_part[288*224];
__device__ __align__(256) float g_lamc_part[(size_t)144*KD*VD];
__device__ __align__(256) float g_lamc[(size_t)B_*KD*VD];
__device__ __align__(256) float g_qaff[2*HK];
__device__ __align__(256) float g_vaff[2*VD];
__device__ __align__(256) float g_lamp[(size_t)GM*GN];

// ---------------- portable PTX helpers ------------------------------------
__device__ __forceinline__ uint32_t smem_u32(const void* p) {
    uint32_t a;
    asm("{ .reg .u64 t; cvta.to.shared.u64 t, %1; cvt.u32.u64 %0, t; }" : "=r"(a) : "l"(p));
    return a;
}
__device__ __forceinline__ void ldmx4(uint32_t* r, uint32_t addr) {
    asm volatile("ldmatrix.sync.aligned.m8n8.x4.shared.b16 {%0,%1,%2,%3}, [%4];"
        : "=r"(r[0]), "=r"(r[1]), "=r"(r[2]), "=r"(r[3]) : "r"(addr));
}
__device__ __forceinline__ void mma16816(float* d, const uint32_t* a, uint32_t b0, uint32_t b1) {
    asm volatile("mma.sync.aligned.m16n8k16.row.col.f32.f16.f16.f32 "
        "{%0,%1,%2,%3}, {%4,%5,%6,%7}, {%8,%9}, {%0,%1,%2,%3};"
        : "+f"(d[0]), "+f"(d[1]), "+f"(d[2]), "+f"(d[3])
        : "r"(a[0]), "r"(a[1]), "r"(a[2]), "r"(a[3]), "r"(b0), "r"(b1));
}
__device__ __forceinline__ void cp16(uint32_t saddr, const void* g) {
    asm volatile("cp.async.cg.shared.global [%0], [%1], 16;" :: "r"(saddr), "l"(g));
}
#define CP_COMMIT() asm volatile("cp.async.commit_group;" ::: "memory")
#define CP_WAIT1()  asm volatile("cp.async.wait_group 1;" ::: "memory")
#define CP_WAIT0()  asm volatile("cp.async.wait_group 0;" ::: "memory")

// ---------------- K1: q/k/v 1x1 conv + BN partials + R convert ------------
__global__ void __launch_bounds__(256) k_proj(const float* __restrict__ x,
                       const float* __restrict__ Wq,
                       const float* __restrict__ Wk,
                       const float* __restrict__ Wv,
                       const float* __restrict__ R) {
    if (blockIdx.x >= 288) {
        int i = (blockIdx.x - 288)*256 + threadIdx.x;
        if (i < RTAB) g_Rh[i] = __half_as_ushort(__float2half_rn(R[i]));
        return;
    }
    __shared__ float Xs[64*33];
    __shared__ float Ws2[112*33];
    __shared__ float red[16*112];
    int t = threadIdx.x;
    int ty = t >> 4, tx = t & 15;
    int row0 = blockIdx.x * 64;
    int bs = blockIdx.x / 36;
    float acc[4][7];
    #pragma unroll
    for (int i = 0; i < 4; i++)
        #pragma unroll
        for (int j = 0; j < 7; j++) acc[i][j] = 0.f;

    for (int k0 = 0; k0 < 128; k0 += 32) {
        for (int e = t; e < 2048; e += 256) {
            int r = e >> 5, k = e & 31;
            Xs[r*33 + k] = x[(size_t)(row0+r)*128 + k0 + k];
        }
        for (int e = t; e < 3584; e += 256) {
            int o = e >> 5, k = e & 31;
            float w;
            if (o < 64)      w = Wq[o*128 + k0 + k];
            else if (o < 80) w = Wk[(o-64)*128 + k0 + k];
            else             w = Wv[(o-80)*128 + k0 + k];
            Ws2[o*33 + k] = w;
        }
        __syncthreads();
        #pragma unroll 8
        for (int kk = 0; kk < 32; kk++) {
            float a[4], b[7];
            #pragma unroll
            for (int i = 0; i < 4; i++) a[i] = Xs[(ty*4+i)*33 + kk];
            #pragma unroll
            for (int j = 0; j < 7; j++) b[j] = Ws2[(tx*7+j)*33 + kk];
            #pragma unroll
            for (int i = 0; i < 4; i++)
                #pragma unroll
                for (int j = 0; j < 7; j++) acc[i][j] += a[i]*b[j];
        }
        __syncthreads();
    }

    int db = (bs + 4) & 7;
    #pragma unroll
    for (int i = 0; i < 4; i++) {
        int row = row0 + ty*4 + i;
        int n = row - bs*NTOK;
        #pragma unroll
        for (int j = 0; j < 7; j++) {
            int o = tx*7 + j;
            float val = acc[i][j];
            if (o < 64)       g_q[(size_t)row*64 + o] = val;
            else if (o < 80)  g_kT[(size_t)(db*16 + o-64)*NTOK + n] = val;
            else              g_v[((size_t)db*NTOK + n)*32 + (o-80)] = val;
        }
    }
    float ps[7], pq[7];
    #pragma unroll
    for (int j = 0; j < 7; j++) {
        ps[j] = acc[0][j]+acc[1][j]+acc[2][j]+acc[3][j];
        pq[j] = acc[0][j]*acc[0][j]+acc[1][j]*acc[1][j]+acc[2][j]*acc[2][j]+acc[3][j]*acc[3][j];
    }
    #pragma unroll
    for (int j = 0; j < 7; j++) red[ty*112 + tx*7 + j] = ps[j];
    __syncthreads();
    if (t < 112) {
        float s = 0.f;
        #pragma unroll
        for (int yy = 0; yy < 16; yy++) s += red[yy*112 + t];
        g_part[blockIdx.x*224 + t] = s;
    }
    __syncthreads();
    #pragma unroll
    for (int j = 0; j < 7; j++) red[ty*112 + tx*7 + j] = pq[j];
    __syncthreads();
    if (t < 112) {
        float s = 0.f;
        #pragma unroll
        for (int yy = 0; yy < 16; yy++) s += red[yy*112 + t];
        g_part[blockIdx.x*224 + 112 + t] = s;
    }
}

// ---------------- K2: reduce BN partials -> affine (parallel) --------------
__global__ void __launch_bounds__(1024) k_affine(const float* __restrict__ gq,
                         const float* __restrict__ bq,
                         const float* __restrict__ gv, const float* __restrict__ bv) {
    __shared__ float s1[8][112], s2[8][112];
    int t = threadIdx.x;
    int grp = t >> 7, ch = t & 127;
    if (ch < 112) {
        float a = 0.f, b2 = 0.f;
        int i0 = grp*36;
        for (int i = i0; i < i0 + 36; i++) {
            a  += g_part[i*224 + ch];
            b2 += g_part[i*224 + 112 + ch];
        }
        s1[grp][ch] = a; s2[grp][ch] = b2;
    }
    __syncthreads();
    if (grp == 0 && ch < 112 && !(ch >= 64 && ch < 80)) {
        float s = 0.f, ss = 0.f;
        #pragma unroll
        for (int g = 0; g < 8; g++) { s += s1[g][ch]; ss += s2[g][ch]; }
        float mu  = s / (float)NROW;
        float var = ss / (float)NROW - mu*mu;
        if (ch < 64) {
            float sc = gq[ch] * rsqrtf(var + 1e-5f);
            g_qaff[ch] = sc; g_qaff[64+ch] = bq[ch] - mu*sc;
        } else {
            int c = ch - 80;
            float sc = gv[c] * rsqrtf(var + 1e-5f);
            g_vaff[c] = sc; g_vaff[32+c] = bv[c] - mu*sc;
        }
    }
}

// ---------------- K3: vt + softmax merged ----------------------------------
__global__ void __launch_bounds__(256) k_vtsoft() {
    __shared__ unsigned short sh[64][33];
    __shared__ float red[256];
    int t = threadIdx.x;
    if (blockIdx.x < 288) {
        int cg = blockIdx.x & 3, mg = blockIdx.x >> 2;   // 4 x 72
        int col0 = cg*64, m0 = mg*32;
        for (int e = t; e < 2048; e += 256) {
            int lm = e >> 6, lc = e & 63;
            int col = col0 + lc;
            int b = col >> 5, v = col & 31;
            int m = m0 + lm;
            float xv = g_v[((size_t)b*NTOK + m)*32 + v] * g_vaff[v] + g_vaff[32+v];
            g_vt[(size_t)m*256 + col] = xv;
            sh[lc][lm] = __half_as_ushort(__float2half_rn(xv));
        }
        __syncthreads();
        int lc = t >> 2, sub = t & 3;
        uint32_t w[4];
        #pragma unroll
        for (int j = 0; j < 4; j++)
            w[j] = (uint32_t)sh[lc][sub*8 + 2*j] | ((uint32_t)sh[lc][sub*8 + 2*j+1] << 16);
        *(uint4*)(g_vthf + (size_t)(col0 + lc)*NTOK + m0 + sub*8) = make_uint4(w[0], w[1], w[2], w[3]);
    } else {
        int bk = blockIdx.x - 288;
        const float* src = g_kT + (size_t)bk*NTOK;
        float r[9];
        #pragma unroll
        for (int i = 0; i < 9; i++) r[i] = src[t + i*256];
        float mx = r[0];
        #pragma unroll
        for (int i = 1; i < 9; i++) mx = fmaxf(mx, r[i]);
        red[t] = mx; __syncthreads();
        for (int s = 128; s > 0; s >>= 1) { if (t < s) red[t] = fmaxf(red[t], red[t+s]); __syncthreads(); }
        mx = red[0]; __syncthreads();
        float sum = 0.f;
        #pragma unroll
        for (int i = 0; i < 9; i++) { r[i] = expf(r[i] - mx); sum += r[i]; }
        red[t] = sum; __syncthreads();
        for (int s = 128; s > 0; s >>= 1) { if (t < s) red[t] += red[t+s]; __syncthreads(); }
        float inv = 1.0f / red[0];
        float* dst = g_ksm + (size_t)bk*NTOK;
        #pragma unroll
        for (int i = 0; i < 9; i++) dst[t + i*256] = r[i] * inv;
    }
}

// ---------------- K5: BIG GEMM (R10 config) + lamc_part in tail -----------
#define TK    64
#define NCH   (GK/TK)      // 36
#define AOFF  0
#define BOFF  16384
#define STG   32768
#define SMEM_MMA (2*STG)   // 65536

__global__ void __launch_bounds__(256, 2) k_lamp_hmma() {
    extern __shared__ char smem[];
    int t = threadIdx.x;

    if (blockIdx.y >= 288) {
        // ---- lamc_part role: 144 blocks, 256 threads --------------------
        float* Ks = (float*)smem;            // 16x128
        float* Vs = (float*)smem + 2048;     // 128x32
        int bid = (blockIdx.y - 288)*2 + blockIdx.x;   // 0..143
        int b = bid / 18, mc = bid - b*18;
        int m0 = mc * 128;
        for (int i = t; i < 2048; i += 256) { int k = i>>7, mm = i&127; Ks[i] = g_ksm[(size_t)(b*16+k)*NTOK + m0+mm]; }
        for (int i = t; i < 4096; i += 256) { int mm = i>>5, v = i&31;  Vs[i] = g_vt[(size_t)(m0+mm)*256 + b*32 + v]; }
        __syncthreads();
        #pragma unroll
        for (int half = 0; half < 2; half++) {
            int idx = half*256 + t;
            int k = idx >> 5, v = idx & 31;
            float acc = 0.f;
            #pragma unroll 8
            for (int mm = 0; mm < 128; mm++) acc += Ks[k*128+mm] * Vs[mm*32+v];
            g_lamc_part[(size_t)bid*512 + idx] = acc;
        }
        return;
    }

    uint32_t sb = smem_u32(smem);
    int nbase = blockIdx.y * 8;
    int col0  = blockIdx.x * 128;

    int n_loc = t >> 5, mi2 = t & 31;
    int n = nbase + n_loc;
    int n_row = n / 48, n_col = n - n_row*48;

    int wid = t >> 5, lane = t & 31;
    int wm = wid >> 1, wn = wid & 1;
    int lr = lane & 15, lc2 = (lane >> 4) * 16;

    float acc[2][8][4];
    #pragma unroll
    for (int i = 0; i < 2; i++)
        #pragma unroll
        for (int j = 0; j < 8; j++)
            #pragma unroll
            for (int q = 0; q < 4; q++) acc[i][j][q] = 0.f;

    uint4 ra0, ra1, rb0, rb1;

    auto ldgA = [&](int c) {
        int ma = c*TK + 2*mi2;
        int mr = ma / 48, mc2 = ma - mr*48;
        const uint4* pa = (const uint4*)(g_Rh + (size_t)((mr - n_row + 47)*95 + (mc2 - n_col + 47)) * 16);
        ra0 = pa[0]; ra1 = pa[1];
        int mb = ma + 1;
        mr = mb / 48; mc2 = mb - mr*48;
        const uint4* pb = (const uint4*)(g_Rh + (size_t)((mr - n_row + 47)*95 + (mc2 - n_col + 47)) * 16);
        rb0 = pb[0]; rb1 = pb[1];
    };
    auto stsA = [&](int p) {
        char* base = smem + p*STG + AOFF;
        uint32_t aw[8] = {ra0.x,ra0.y,ra0.z,ra0.w,ra1.x,ra1.y,ra1.z,ra1.w};
        uint32_t bw[8] = {rb0.x,rb0.y,rb0.z,rb0.w,rb1.x,rb1.y,rb1.z,rb1.w};
        uint32_t cb = (uint32_t)mi2 * 4;
        #pragma unroll
        for (int i = 0; i < 8; i++) {
            uint32_t w0 = __byte_perm(aw[i], bw[i], 0x5410);
            uint32_t w1 = __byte_perm(aw[i], bw[i], 0x7632);
            uint32_t r0 = (uint32_t)(n_loc*16 + 2*i);
            uint32_t r1 = r0 + 1;
            *(uint32_t*)(base + ((r0*128u + cb) ^ ((r0 & 7u) << 4))) = w0;
            *(uint32_t*)(base + ((r1*128u + cb) ^ ((r1 & 7u) << 4))) = w1;
        }
    };
    auto cpB = [&](int c, int p) {
        int m0 = c * TK;
        uint32_t sa = sb + p*STG + BOFF;
        #pragma unroll
        for (int i = 0; i < 4; i++) {
            int idx = t*4 + i;
            uint32_t col = (uint32_t)(idx >> 3), ch = (uint32_t)(idx & 7);
            uint32_t off = (col*128u + ch*16u) ^ ((col & 7u) << 4);
            cp16(sa + off, g_vthf + (size_t)(col0 + col)*NTOK + m0 + ch*8);
        }
    };

    // prologue
    ldgA(0); cpB(0, 0); CP_COMMIT(); stsA(0);
    ldgA(1); cpB(1, 1); CP_COMMIT();
    CP_WAIT1();
    __syncthreads();

    int p = 0;
    for (int c = 0; c < NCH; c++) {
        uint32_t sa = sb + p*STG;
        #pragma unroll
        for (int kk = 0; kk < 4; kk++) {
            uint32_t kb = (uint32_t)(kk * 32);
            uint32_t aa[8], bb[16];
            #pragma unroll
            for (int mf = 0; mf < 2; mf++) {
                uint32_t row = (uint32_t)(wm*32 + mf*16 + lr);
                uint32_t off = (row*128u + kb + (uint32_t)lc2) ^ ((row & 7u) << 4);
                ldmx4(aa + mf*4, sa + AOFF + off);
            }
            #pragma unroll
            for (int ng = 0; ng < 4; ng++) {
                uint32_t row = (uint32_t)(wn*64 + ng*16 + lr);
                uint32_t off = (row*128u + kb + (uint32_t)lc2) ^ ((row & 7u) << 4);
                ldmx4(bb + ng*4, sa + BOFF + off);
            }
            #pragma unroll
            for (int mf = 0; mf < 2; mf++)
                #pragma unroll
                for (int nf = 0; nf < 8; nf++)
                    mma16816(acc[mf][nf], aa + mf*4, bb[(nf>>1)*4 + (nf&1)], bb[(nf>>1)*4 + (nf&1) + 2]);
        }
        if (c + 1 < NCH) stsA(1 - p);
        if (c + 2 < NCH) ldgA(c + 2);
        CP_WAIT0();
        __syncthreads();
        if (c + 2 < NCH) { cpB(c + 2, p); CP_COMMIT(); }
        p ^= 1;
    }

    #pragma unroll
    for (int mf = 0; mf < 2; mf++) {
        #pragma unroll
        for (int nf = 0; nf < 8; nf++) {
            int r0 = blockIdx.y*128 + wm*32 + mf*16 + (lane >> 2);
            int c0 = col0 + wn*64 + nf*8 + (lane & 3)*2;
            *(float2*)&g_lamp[(size_t)r0*256 + c0]     = make_float2(acc[mf][nf][0], acc[mf][nf][1]);
            *(float2*)&g_lamp[(size_t)(r0+8)*256 + c0] = make_float2(acc[mf][nf][2], acc[mf][nf][3]);
        }
    }
}

// ---------------- K5b: lamc reduce -----------------------------------------
__global__ void k_lamc_red() {
    int b = blockIdx.x, t = threadIdx.x;
    float s = 0.f;
    for (int mc = 0; mc < 18; mc++) s += g_lamc_part[(size_t)(b*18+mc)*512 + t];
    g_lamc[b*512 + t] = s;
}

// ---------------- K6: fused consumers (32 rows/block, warp-per-row) -------
__global__ void __launch_bounds__(256) k_out(const float* __restrict__ cor,
                       const float* __restrict__ Wce, const float* __restrict__ bce,
                       const float* __restrict__ Wcc, const float* __restrict__ Wmp,
                       const float* __restrict__ bmp,
                       float* __restrict__ app, float* __restrict__ mot) {
    __shared__ float WccS[64*129];   // [o][c] padded
    __shared__ float WmpS[128*65];   // [o][c] padded
    __shared__ float WceS[128];
    __shared__ float bceS[64];
    __shared__ float bmpS[128];
    __shared__ float lamcS[512];
    int t = threadIdx.x;
    int b = blockIdx.x / 72;         // 72 blocks per batch (32 rows each)

    for (int i = t; i < 8192; i += 256) WccS[(i>>7)*129 + (i&127)] = Wcc[i];
    for (int i = t; i < 8192; i += 256) WmpS[(i>>6)*65 + (i&63)]   = Wmp[i];
    if (t < 128) WceS[t] = Wce[t];
    if (t < 64)  bceS[t] = bce[t];
    if (t < 128) bmpS[t] = bmp[t];
    for (int i = t; i < 512; i += 256) lamcS[i] = g_lamc[b*512 + i];
    __syncthreads();

    int w = t >> 5, lane = t & 31;
    for (int it = 0; it < 4; it++) {
        int row = blockIdx.x*32 + it*8 + w;
        int n = row - b*NTOK;

        float q0 = g_q[(size_t)row*64 + lane]      * g_qaff[lane]    + g_qaff[64+lane];
        float q1 = g_q[(size_t)row*64 + 32 + lane] * g_qaff[32+lane] + g_qaff[96+lane];
        float c0 = cor[(size_t)row*2], c1 = cor[(size_t)row*2 + 1];
        float ce0 = c0*WceS[lane*2]      + c1*WceS[lane*2+1]      + bceS[lane];
        float ce1 = c0*WceS[(32+lane)*2] + c1*WceS[(32+lane)*2+1] + bceS[32+lane];

        float y[4] = {0.f,0.f,0.f,0.f}, cr[4] = {0.f,0.f,0.f,0.f};
        const float* lp = g_lamp + (size_t)(n*16)*256 + b*32 + lane;
        #pragma unroll
        for (int k = 0; k < 16; k++) {
            float l = lp[(size_t)k*256] + lamcS[k*32 + lane];
            y[0]  += __shfl_sync(0xffffffffu, q0, k)      * l;
            y[1]  += __shfl_sync(0xffffffffu, q0, 16 + k) * l;
            y[2]  += __shfl_sync(0xffffffffu, q1, k)      * l;
            y[3]  += __shfl_sync(0xffffffffu, q1, 16 + k) * l;
            cr[0] += __shfl_sync(0xffffffffu, ce0, k)      * l;
            cr[1] += __shfl_sync(0xffffffffu, ce0, 16 + k) * l;
            cr[2] += __shfl_sync(0xffffffffu, ce1, k)      * l;
            cr[3] += __shfl_sync(0xffffffffu, ce1, 16 + k) * l;
        }
        #pragma unroll
        for (int h = 0; h < 4; h++)
            app[(size_t)row*128 + h*32 + lane] = y[h];

        float d0 = -ce0, d1 = -ce1;
        #pragma unroll 4
        for (int c = 0; c < 128; c++) {
            float crc = __shfl_sync(0xffffffffu, cr[c >> 5], c & 31);
            d0 += crc * WccS[lane*129 + c];
            d1 += crc * WccS[(32+lane)*129 + c];
        }

        float m[4] = {bmpS[lane], bmpS[32+lane], bmpS[64+lane], bmpS[96+lane]};
        #pragma unroll 8
        for (int c = 0; c < 32; c++) {
            float dc = __shfl_sync(0xffffffffu, d0, c);
            #pragma unroll
            for (int h = 0; h < 4; h++) m[h] += dc * WmpS[(h*32+lane)*65 + c];
        }
        #pragma unroll 8
        for (int c = 0; c < 32; c++) {
            float dc = __shfl_sync(0xffffffffu, d1, c);
            #pragma unroll
            for (int h = 0; h < 4; h++) m[h] += dc * WmpS[(h*32+lane)*65 + 32 + c];
        }
        #pragma unroll
        for (int h = 0; h < 4; h++)
            mot[(size_t)row*128 + h*32 + lane] = m[h];
    }
}

// ---------------- launch ---------------------------------------------------
extern "C" void kernel_launch(void* const* d_in, const int* in_sizes, int n_in,
                              void* d_out, int out_size) {
    const float* x   = (const float*)d_in[0];
    const float* cor = (const float*)d_in[1];
    const float* Wq  = (const float*)d_in[2];
    const float* Wk  = (const float*)d_in[3];
    const float* Wv  = (const float*)d_in[4];
    const float* Wce = (const float*)d_in[5];
    const float* bce = (const float*)d_in[6];
    const float* Wcc = (const float*)d_in[7];
    const float* Wmp = (const float*)d_in[8];
    const float* bmp = (const float*)d_in[9];
    const float* gq  = (const float*)d_in[10];
    const float* bq  = (const float*)d_in[11];
    const float* gv  = (const float*)d_in[12];
    const float* bv  = (const float*)d_in[13];
    const float* rpe = (const float*)d_in[14];
    float* app = (float*)d_out;
    float* mot = app + (size_t)NROW*128;

    cudaFuncSetAttribute(k_lamp_hmma, cudaFuncAttributeMaxDynamicSharedMemorySize, SMEM_MMA);

    k_proj<<<288 + (RTAB + 255)/256, 256>>>(x, Wq, Wk, Wv, rpe);  // #1
    k_affine<<<1, 1024>>>(gq, bq, gv, bv);                         // #2
    k_vtsoft<<<416, 256>>>();                                      // #3
    k_lamp_hmma<<<dim3(2, 360), 256, SMEM_MMA>>>();                // #4 <- profiled (incl. lamc_part tail)
    k_lamc_red<<<8, 512>>>();                                      // #5
    k_out<<<576, 256>>>(cor, Wce, bce, Wcc, Wmp, bmp, app, mot);   // #6
}